// round 5
// baseline (speedup 1.0000x reference)
#include <cuda_runtime.h>
#include <math.h>
#include <math_constants.h>

#define NS 4760
#define KNN 16
#define NB 16
#define NT 6

// ------------------------- device scratch -------------------------
__device__ float g_q  [NS*128];      // query features
__device__ float g_Wpack[128*328];   // packed fused weights, row k, 328-stride
__device__ float g_bpack[328];       // packed biases
__device__ float g_ql [NS*64];
__device__ float g_sp [NS*64];
__device__ float g_spW[NS*64];
__device__ float g_qg [NS*128];
__device__ float g_a0 [NS];
__device__ float g_a1 [NS];
__device__ float g_kg [NB*NT*128];
__device__ float g_vgo [NB*25*128];
__device__ float g_vgoW[NB*25*64];
__device__ float g_sumv[NB*25];
__device__ float g_gram[NB*25*25];
__device__ float g_ga  [(size_t)NS*NB*24];   // normalized global attention, row order t*4+h
__device__ float g_cst [256];   // [w0W(64) w1W(64) gcol(64) cadd(64)]

__device__ __forceinline__ float wsum(float v){
    #pragma unroll
    for (int o=16;o;o>>=1) v += __shfl_xor_sync(0xffffffffu, v, o);
    return v;
}
__device__ __forceinline__ float wmax(float v){
    #pragma unroll
    for (int o=16;o;o>>=1) v = fmaxf(v, __shfl_xor_sync(0xffffffffu, v, o));
    return v;
}
template<int N>
__device__ __forceinline__ void wsumv(float* v){
    #pragma unroll
    for (int o=16;o;o>>=1){
        #pragma unroll
        for (int i=0;i<N;i++) v[i] += __shfl_xor_sync(0xffffffffu, v[i], o);
    }
}

// ------------------------- kPrep: latent path (0-95) | weight pack (96) | q build (97+) ----
__global__ void __launch_bounds__(256,1) kPrep(
    const float* __restrict__ pos, const float* __restrict__ femb, const int* __restrict__ fid,
    const float* __restrict__ Wnbr, const float* __restrict__ bnbr,
    const float* __restrict__ Wql,  const float* __restrict__ bql,
    const float* __restrict__ Wqg,  const float* __restrict__ bqg,
    const float* __restrict__ lng,  const float* __restrict__ lnb,
    const float* __restrict__ Wm1,  const float* __restrict__ bm1,
    const float* __restrict__ latent,
    const float* __restrict__ Wlat, const float* __restrict__ blat,
    const float* __restrict__ Wlf,  const float* __restrict__ blf,
    const float* __restrict__ Wk,   const float* __restrict__ bk,
    const float* __restrict__ Wv,   const float* __restrict__ bv,
    const float* __restrict__ Wgo,  const float* __restrict__ bgo)
{
    __shared__ float sbuf[4608];
    int tid = threadIdx.x;

    if (blockIdx.x < 96){
        // ======== latent path ========
        float* lat_s  = sbuf;           // 1056
        float* part_s = sbuf + 1056;    // 256
        float* kv_s   = sbuf + 1312;    // 128
        float* vg_s   = sbuf + 1440;    // 128
        int idx = blockIdx.x;
        int t = idx % NT, b = idx / NT;
        for (int e=tid;e<1024;e+=256) lat_s[e] = latent[((size_t)b*NT+t)*1024 + e];
        if (tid<32) lat_s[1024+tid] = femb[t*32+tid];
        __syncthreads();

        int j = tid & 127, half = tid >> 7;
        float acc = half ? 0.f : (blat[j] + blf[j]);
        if (half == 0){
            #pragma unroll 4
            for (int i=0;i<512;i++) acc = fmaf(lat_s[i], Wlat[i*128+j], acc);
        } else {
            #pragma unroll 4
            for (int i=512;i<1024;i++) acc = fmaf(lat_s[i], Wlat[i*128+j], acc);
            for (int f=0;f<32;f++)     acc = fmaf(lat_s[1024+f], Wlf[f*128+j], acc);
        }
        part_s[half*128 + j] = acc;
        __syncthreads();
        if (tid < 128) kv_s[tid] = part_s[tid] + part_s[128+tid];
        __syncthreads();

        {
            const float* W  = half ? Wv : Wk;
            float o = half ? bv[j] : bk[j];
            #pragma unroll 4
            for (int i=0;i<128;i++) o = fmaf(kv_s[i], W[i*128+j], o);
            if (half == 0) g_kg[(b*NT+t)*128 + j] = o;
            else           vg_s[j] = o;
        }
        __syncthreads();

        for (int o2=tid;o2<512;o2+=256){
            int h = o2 >> 7, j2 = o2 & 127;
            float a = 0.f;
            #pragma unroll
            for (int d=0;d<32;d++) a = fmaf(vg_s[h*32+d], Wgo[(h*32+d)*128+j2], a);
            g_vgo[((size_t)b*25 + t*4 + h)*128 + j2] = a;
        }
        if (t==0){
            for (int j2=tid;j2<128;j2+=256) g_vgo[((size_t)b*25 + 24)*128 + j2] = bgo[j2];
        }
        return;
    }

    if (blockIdx.x == 96){
        // ======== weight/bias pack + consts ========
        float* W1t = sbuf;   // 4096: lng[i]*Wm1[i][j], i<64
        for (int e=tid;e<4096;e+=256) W1t[e] = lng[e>>6]*Wm1[e];
        __syncthreads();

        // direct copies into pack
        for (int e=tid;e<8192;e+=256){
            int k=e>>6, j=e&63;
            g_Wpack[k*328 + j]      = Wql[e];
            g_Wpack[k*328 + 64 + j] = Wnbr[128+e];
        }
        for (int e=tid;e<16384;e+=256){
            int k=e>>7, j=e&127;
            g_Wpack[k*328 + 128 + j] = Wqg[e];
        }
        // fused spW weight: Wnb' @ W1t  [128x64]
        for (int e=tid;e<8192;e+=256){
            int c=e>>6, j=e&63;
            float a = 0.f;
            #pragma unroll 4
            for (int i=0;i<64;i++) a = fmaf(Wnbr[128 + c*64 + i], W1t[i*64+j], a);
            g_Wpack[c*328 + 256 + j] = a;
        }
        // a0/a1 fused weights
        if (tid < 256){
            int k = tid & 127, which = tid >> 7;
            float a = 0.f;
            for (int i=0;i<64;i++) a = fmaf(Wql[k*64+i], Wnbr[which*64 + i], a);
            g_Wpack[k*328 + 320 + which] = a;
        }
        // biases
        if (tid < 64){
            g_bpack[tid]      = bql[tid];
            g_bpack[64+tid]   = bnbr[tid];
            float bf = 0.f;
            for (int i=0;i<64;i++) bf = fmaf(bnbr[i], W1t[i*64+tid], bf);
            g_bpack[256+tid] = bf;
        }
        if (tid < 128) g_bpack[128+tid] = bqg[tid];
        if (tid == 0){
            float a0=0.f, a1=0.f;
            for (int i=0;i<64;i++){ a0 = fmaf(bql[i], Wnbr[i], a0); a1 = fmaf(bql[i], Wnbr[64+i], a1); }
            g_bpack[320] = a0; g_bpack[321] = a1;
        }
        // consts
        if (tid < 64){
            int j = tid;
            float w0W=0.f, w1W=0.f, gcol=0.f, cadd=0.f;
            for (int i=0;i<192;i++){
                float w = Wm1[i*64+j];
                gcol += lng[i]*w;
                cadd += lnb[i]*w;
            }
            for (int i=0;i<64;i++){
                float w = lng[i]*Wm1[i*64+j];
                w0W += Wnbr[i]     * w;
                w1W += Wnbr[64+i]  * w;
            }
            g_cst[j]      = w0W;
            g_cst[64+j]   = w1W;
            g_cst[128+j]  = gcol;
            g_cst[192+j]  = cadd + bm1[j];
        }
        return;
    }

    // ======== query matrix build: blocks 97.. , 256 sensors each ========
    {
        int n0 = (blockIdx.x - 97) * 256;
        for (int e=tid;e<256*128;e+=256){
            int s = e>>7, k = e&127, n = n0 + s;
            if (n >= NS) break;
            g_q[n*128 + k] = (k<96) ? pos[n*96+k] : femb[fid[n]*32 + (k-96)];
        }
    }
}

// ------------------------- kGEMM: [4760x128]@[128x322] -------------------------
__global__ void __launch_bounds__(256,1) kGEMM(){
    __shared__ float AT[128*68];   // A transposed [k][sensor], pad 68
    int tid = threadIdx.x;
    int n0 = blockIdx.x * 64;
    int c0 = blockIdx.y * 64;

    for (int e=tid;e<64*128;e+=256){
        int s = e>>7, k = e&127, n = n0+s;
        AT[k*68 + s] = (n<NS) ? g_q[n*128 + k] : 0.f;
    }
    __syncthreads();

    int cg = tid & 15, sg = tid >> 4;
    int cbase = c0 + cg*4;
    if (cbase > 324) cbase = 324;     // clamp for tail tile (reads stay in-bounds)

    const float4* Wb = (const float4*)(g_Wpack + cbase);   // stride 82 float4
    const float4* Ab = (const float4*)(AT) + sg;           // stride 17 float4

    float acc[4][4];
    #pragma unroll
    for (int s=0;s<4;s++){ acc[s][0]=0.f; acc[s][1]=0.f; acc[s][2]=0.f; acc[s][3]=0.f; }

    #pragma unroll 4
    for (int k=0;k<128;k++){
        float4 w = Wb[k*82];
        float4 a = Ab[k*17];
        float av[4] = {a.x, a.y, a.z, a.w};
        #pragma unroll
        for (int s=0;s<4;s++){
            acc[s][0] = fmaf(av[s], w.x, acc[s][0]);
            acc[s][1] = fmaf(av[s], w.y, acc[s][1]);
            acc[s][2] = fmaf(av[s], w.z, acc[s][2]);
            acc[s][3] = fmaf(av[s], w.w, acc[s][3]);
        }
    }

    #pragma unroll
    for (int s=0;s<4;s++){
        int n = n0 + sg*4 + s;
        if (n >= NS) continue;
        #pragma unroll
        for (int u=0;u<4;u++){
            int c = c0 + cg*4 + u;
            if (c >= 322) continue;
            float v = acc[s][u] + g_bpack[c];
            if (c < 64)        g_ql [n*64 + c]        = v;
            else if (c < 128)  g_sp [n*64 + (c-64)]   = v;
            else if (c < 256)  g_qg [n*128 + (c-128)] = v;
            else if (c < 320)  g_spW[n*64 + (c-256)]  = v;
            else if (c == 320) g_a0[n] = v;
            else               g_a1[n] = v;
        }
    }
}

// ------------------------- kF2: global logits+softmax (h<4) | batch folds (h==4) ----
__global__ void __launch_bounds__(256,1) kF2(const float* __restrict__ lng, const float* __restrict__ Wm1){
    extern __shared__ float sm[];
    int tid = threadIdx.x;
    int h = blockIdx.y;

    if (h < 4){
        float* Qs = sm;          // 128*33 = 4224
        float* Ks = sm + 4224;   // 96*33  = 3168
        int n0 = blockIdx.x * 128;

        for (int e=tid;e<4096;e+=256){
            int r=e>>5, k=e&31, n=n0+r;
            Qs[r*33+k] = (n<NS) ? g_qg[n*128 + h*32 + k] : 0.f;
        }
        for (int e=tid;e<3072;e+=256){
            int c=e>>5, k=e&31;
            Ks[c*33+k] = g_kg[c*128 + h*32 + k];
        }
        __syncthreads();

        int cg = tid & 15;          // batch
        int r0 = (tid >> 4)*8;
        float acc[8][6];
        #pragma unroll
        for (int s=0;s<8;s++)
            #pragma unroll
            for (int u=0;u<6;u++) acc[s][u]=0.f;

        #pragma unroll 4
        for (int k=0;k<32;k++){
            float qv[8], kv[6];
            #pragma unroll
            for (int s=0;s<8;s++) qv[s] = Qs[(r0+s)*33 + k];
            #pragma unroll
            for (int u=0;u<6;u++) kv[u] = Ks[(cg*6+u)*33 + k];
            #pragma unroll
            for (int s=0;s<8;s++)
                #pragma unroll
                for (int u=0;u<6;u++) acc[s][u] = fmaf(qv[s], kv[u], acc[s][u]);
        }

        const float scale = 0.17677669529663687f;
        #pragma unroll
        for (int s=0;s<8;s++){
            int n = n0 + r0 + s;
            if (n >= NS) continue;
            float m = -CUDART_INF_F;
            #pragma unroll
            for (int u=0;u<6;u++) m = fmaxf(m, acc[s][u]);
            float e[6], den = 0.f;
            #pragma unroll
            for (int u=0;u<6;u++){ e[u] = __expf((acc[s][u]-m)*scale); den += e[u]; }
            float inv = 1.f/den;
            float* dst = g_ga + ((size_t)n*16 + cg)*24;
            #pragma unroll
            for (int u=0;u<6;u++) dst[u*4 + h] = e[u]*inv;
        }
    } else {
        // ======== batch folds, 38 blocks x 8 warps = 304 warps ========
        float* w1bT = sm;   // 64*132 = 8448
        for (int e=tid;e<8192;e+=256){ int c=e>>6, j=e&63; w1bT[j*132+c] = lng[64+c]*Wm1[4096+e]; }
        __syncthreads();

        int lane = tid & 31, c4 = lane*4;
        int gw = blockIdx.x*8 + (tid>>5);

        for (int task=gw; task<36000; task+=304){
            int b = task/2250, tt = task - b*2250;
            if (tt < 1600){
                int i = tt >> 6, j = tt & 63;
                float4 a = *(const float4*)(g_vgo + ((size_t)b*25+i)*128 + c4);
                float4 w = *(const float4*)(w1bT + j*132 + c4);
                float v = a.x*w.x + a.y*w.y + a.z*w.z + a.w*w.w;
                v = wsum(v);
                if (lane==0) g_vgoW[(b*25+i)*64 + j] = v;
            } else if (tt < 2225){
                int p = tt - 1600, i1 = p/25, i2 = p - i1*25;
                float4 a = *(const float4*)(g_vgo + ((size_t)b*25+i1)*128 + c4);
                float4 c = *(const float4*)(g_vgo + ((size_t)b*25+i2)*128 + c4);
                float v = a.x*c.x + a.y*c.y + a.z*c.z + a.w*c.w;
                v = wsum(v);
                if (lane==0) g_gram[b*625 + p] = v;
            } else {
                int i = tt - 2225;
                float4 a = *(const float4*)(g_vgo + ((size_t)b*25+i)*128 + c4);
                float v = a.x + a.y + a.z + a.w;
                v = wsum(v);
                if (lane==0) g_sumv[b*25 + i] = v;
            }
        }
    }
}

// ------------------------- kG: fused main -------------------------
__global__ void __launch_bounds__(512,1) kG(
    const float* __restrict__ xf, const int* __restrict__ mask, const int* __restrict__ knn,
    const float* __restrict__ Wnbr, const float* __restrict__ Wm2, const float* __restrict__ bm2,
    float* __restrict__ out)
{
    extern __shared__ float sm[];
    float* vgoW_s = sm;            // 25600
    float* gram_s = sm + 25600;    // 10000
    float* sumv_s = sm + 35600;    // 400
    float* cst    = sm + 36000;    // 448
    int tid = threadIdx.x;
    for (int e=tid;e<25600;e+=512) vgoW_s[e] = g_vgoW[e];
    for (int e=tid;e<10000;e+=512) gram_s[e] = g_gram[e];
    if (tid < 400) sumv_s[tid] = g_sumv[tid];
    if (tid < 128) cst[tid] = Wnbr[tid];
    if (tid >= 128 && tid < 384) cst[tid] = g_cst[tid-128];
    if (tid >= 384 && tid < 448) cst[tid] = Wm2[tid-384];
    __syncthreads();
    const float* w0_s  = cst;
    const float* w1_s  = cst + 64;
    const float* w0W_s = cst + 128;
    const float* w1W_s = cst + 192;
    const float* gcol_s= cst + 256;
    const float* cadd_s= cst + 320;
    const float* wm2_s = cst + 384;

    const unsigned FULL = 0xffffffffu;
    int wid = tid >> 5, lane = tid & 31;
    float bm2v = bm2[0];

    for (int n = blockIdx.x*16 + wid; n < NS; n += gridDim.x*16){
        int kj = 0;
        if (lane < 16) kj = knn[n*16 + lane];
        float a0 = g_a0[n], a1 = g_a1[n];
        float ql0 = g_ql[n*64 + lane], ql1 = g_ql[n*64 + 32 + lane];
        float rsp0[16], rsp1[16], rw0[16], rw1[16];
        #pragma unroll
        for (int k=0;k<16;k++){
            int j = __shfl_sync(FULL, kj, k);
            rsp0[k] = g_sp[j*64 + lane];
            rsp1[k] = g_sp[j*64 + 32 + lane];
            rw0[k]  = g_spW[j*64 + lane];
            rw1[k]  = g_spW[j*64 + 32 + lane];
        }
        float Sreg = 0.f;
        #pragma unroll
        for (int k0=0;k0<16;k0+=4){
            float p[4];
            #pragma unroll
            for (int u=0;u<4;u++) p[u] = fmaf(rsp0[k0+u], ql0, rsp1[k0+u]*ql1);
            wsumv<4>(p);
            if (lane == k0)   Sreg = p[0];
            if (lane == k0+1) Sreg = p[1];
            if (lane == k0+2) Sreg = p[2];
            if (lane == k0+3) Sreg = p[3];
        }

        for (int b=0;b<16;b++){
            // hoisted independent loads
            int mn = mask[b*NS + n];
            float gaR;
            if (lane < 24)       gaR = g_ga[((size_t)n*16 + b)*24 + lane];
            else if (lane == 24) gaR = 1.f;
            else                 gaR = 0.f;

            // ---- local attention ----
            float x0 = 0.f, x1 = 0.f, logit = -CUDART_INF_F;
            if (lane < 16){
                float2 xv = *(const float2*)(xf + (size_t)(b*NS + kj)*2);
                x0 = xv.x; x1 = xv.y;
                int mk = mask[b*NS + kj];
                logit = (mk != 0) ? -10000.f : (Sreg + x0*a0 + x1*a1)*0.125f;
            }
            float mx  = wmax(logit);
            float red3[3];
            float e = (lane < 16) ? __expf(logit - mx) : 0.f;
            red3[0] = e; red3[1] = e*x0; red3[2] = e*x1;
            wsumv<3>(red3);
            float inv = 1.f/red3[0];
            float attn = e*inv;
            float alpha = red3[1]*inv, beta = red3[2]*inv;

            float L0 = alpha*w0_s[lane]      + beta*w1_s[lane];
            float L1 = alpha*w0_s[32+lane]   + beta*w1_s[32+lane];
            float P0 = alpha*w0W_s[lane]     + beta*w1W_s[lane];
            float P1 = alpha*w0W_s[32+lane]  + beta*w1W_s[32+lane];
            #pragma unroll
            for (int k=0;k<16;k++){
                float ak = __shfl_sync(FULL, attn, k);
                L0 = fmaf(ak, rsp0[k], L0);
                L1 = fmaf(ak, rsp1[k], L1);
                P0 = fmaf(ak, rw0[k],  P0);
                P1 = fmaf(ak, rw1[k],  P1);
            }
            float redL[2];
            redL[0] = L0 + L1;
            redL[1] = L0*L0 + L1*L1;
            wsumv<2>(redL);
            float sL = redL[0], sL2 = redL[1];

            // ---- global attention (normalized weights precomputed) ----
            int rowi = (lane < 25) ? lane : 0;
            float rowd = 0.f;
            #pragma unroll
            for (int i2=0;i2<25;i2++){
                float gv = __shfl_sync(FULL, gaR, i2);
                rowd = fmaf(gv, gram_s[(b*25 + rowi)*25 + i2], rowd);
            }
            float redG[2];
            redG[0] = gaR * sumv_s[b*25 + rowi];
            redG[1] = gaR * rowd;
            wsumv<2>(redG);
            float sumg = redG[0], sumg2 = redG[1];

            float Pg0 = 0.f, Pg1 = 0.f;
            #pragma unroll
            for (int i=0;i<25;i++){
                float gv = __shfl_sync(FULL, gaR, i);
                Pg0 = fmaf(gv, vgoW_s[(b*25+i)*64 + lane],      Pg0);
                Pg1 = fmaf(gv, vgoW_s[(b*25+i)*64 + 32 + lane], Pg1);
            }

            // ---- LN + MLP fold ----
            float mean = (sL + sumg)*(1.f/192.f);
            float var  = (sL2 + sumg2)*(1.f/192.f) - mean*mean;
            float rstd = rsqrtf(var + 1e-5f);
            float h0 = fmaf(rstd, (P0+Pg0) - mean*gcol_s[lane],    cadd_s[lane]);
            float h1 = fmaf(rstd, (P1+Pg1) - mean*gcol_s[32+lane], cadd_s[32+lane]);
            float gelu0 = 0.5f*h0*(1.f + erff(h0*0.70710678118654752f));
            float gelu1 = 0.5f*h1*(1.f + erff(h1*0.70710678118654752f));
            float pr = wsum(fmaf(gelu0, wm2_s[lane], gelu1*wm2_s[32+lane]));
            if (lane == 0){
                out[b*NS + n] = mn ? (pr + bm2v) : 0.f;
            }
        }
    }
}

// ------------------------- launch -------------------------
extern "C" void kernel_launch(void* const* d_in, const int* in_sizes, int n_in,
                              void* d_out, int out_size){
    const float* xf    = (const float*)d_in[0];
    const float* latent= (const float*)d_in[1];
    const float* pos   = (const float*)d_in[2];
    const float* femb  = (const float*)d_in[3];
    const float* Wnbr  = (const float*)d_in[4];
    const float* bnbr  = (const float*)d_in[5];
    const float* Wql   = (const float*)d_in[6];
    const float* bql   = (const float*)d_in[7];
    const float* Wlat  = (const float*)d_in[8];
    const float* blat  = (const float*)d_in[9];
    const float* Wlf   = (const float*)d_in[10];
    const float* blf   = (const float*)d_in[11];
    const float* Wqg   = (const float*)d_in[12];
    const float* bqg   = (const float*)d_in[13];
    const float* Wk    = (const float*)d_in[14];
    const float* bk    = (const float*)d_in[15];
    const float* Wv    = (const float*)d_in[16];
    const float* bv    = (const float*)d_in[17];
    const float* Wgo   = (const float*)d_in[18];
    const float* bgo   = (const float*)d_in[19];
    const float* lng   = (const float*)d_in[20];
    const float* lnb   = (const float*)d_in[21];
    const float* Wm1   = (const float*)d_in[22];
    const float* bm1   = (const float*)d_in[23];
    const float* Wm2   = (const float*)d_in[24];
    const float* bm2   = (const float*)d_in[25];
    const int* mask    = (const int*)d_in[26];
    const int* knn     = (const int*)d_in[27];
    const int* fid     = (const int*)d_in[28];
    float* out = (float*)d_out;

    cudaFuncSetAttribute(kF2, cudaFuncAttributeMaxDynamicSharedMemorySize, 8448*4);
    cudaFuncSetAttribute(kG,  cudaFuncAttributeMaxDynamicSharedMemorySize, 36448*4);

    kPrep<<<116,256>>>(pos, femb, fid, Wnbr, bnbr, Wql, bql, Wqg, bqg, lng, lnb, Wm1, bm1,
                       latent, Wlat, blat, Wlf, blf, Wk, bk, Wv, bv, Wgo, bgo);
    kGEMM<<<dim3(75,6),256>>>();
    kF2<<<dim3(38,5),256,8448*4>>>(lng, Wm1);
    kG<<<149,512,36448*4>>>(xf, mask, knn, Wnbr, Wm2, bm2, out);
}

// round 6
// speedup vs baseline: 1.1067x; 1.1067x over previous
#include <cuda_runtime.h>
#include <math.h>
#include <math_constants.h>

#define NS 4760
#define KNN 16
#define NB 16
#define NT 6

// ------------------------- device scratch -------------------------
__device__ float g_q  [NS*128];      // query features
__device__ float g_Wpack[128*328];   // packed fused weights
__device__ float g_bpack[328];       // packed biases
__device__ float g_ql [NS*64];
__device__ float g_sp [NS*64];
__device__ float g_spW[NS*64];
__device__ float g_qg [NS*128];
__device__ float g_a0 [NS];
__device__ float g_a1 [NS];
__device__ float g_kg [NB*NT*128];
__device__ float g_vgo [NB*25*128];
__device__ float g_vgoW[NB*25*64];
__device__ float g_sumv[NB*25];
__device__ float g_gram[NB*25*25];
__device__ float g_pg  [(size_t)NS*NB*68];   // per (n,b): Pg[64], sumg, sumg2
__device__ float g_cst [256];   // [w0W(64) w1W(64) gcol(64) cadd(64)]

__device__ __forceinline__ float wsum(float v){
    #pragma unroll
    for (int o=16;o;o>>=1) v += __shfl_xor_sync(0xffffffffu, v, o);
    return v;
}
__device__ __forceinline__ float wmax(float v){
    #pragma unroll
    for (int o=16;o;o>>=1) v = fmaxf(v, __shfl_xor_sync(0xffffffffu, v, o));
    return v;
}
template<int N>
__device__ __forceinline__ void wsumv(float* v){
    #pragma unroll
    for (int o=16;o;o>>=1){
        #pragma unroll
        for (int i=0;i<N;i++) v[i] += __shfl_xor_sync(0xffffffffu, v[i], o);
    }
}

// ------------------------- kPrep: latent path (0-95) | weight pack (96) | q build (97+) ----
__global__ void __launch_bounds__(256,1) kPrep(
    const float* __restrict__ pos, const float* __restrict__ femb, const int* __restrict__ fid,
    const float* __restrict__ Wnbr, const float* __restrict__ bnbr,
    const float* __restrict__ Wql,  const float* __restrict__ bql,
    const float* __restrict__ Wqg,  const float* __restrict__ bqg,
    const float* __restrict__ lng,  const float* __restrict__ lnb,
    const float* __restrict__ Wm1,  const float* __restrict__ bm1,
    const float* __restrict__ latent,
    const float* __restrict__ Wlat, const float* __restrict__ blat,
    const float* __restrict__ Wlf,  const float* __restrict__ blf,
    const float* __restrict__ Wk,   const float* __restrict__ bk,
    const float* __restrict__ Wv,   const float* __restrict__ bv,
    const float* __restrict__ Wgo,  const float* __restrict__ bgo)
{
    __shared__ float sbuf[4608];
    int tid = threadIdx.x;

    if (blockIdx.x < 96){
        // ======== latent path ========
        float* lat_s  = sbuf;           // 1056
        float* part_s = sbuf + 1056;    // 256
        float* kv_s   = sbuf + 1312;    // 128
        float* vg_s   = sbuf + 1440;    // 128
        int idx = blockIdx.x;
        int t = idx % NT, b = idx / NT;
        for (int e=tid;e<1024;e+=256) lat_s[e] = latent[((size_t)b*NT+t)*1024 + e];
        if (tid<32) lat_s[1024+tid] = femb[t*32+tid];
        __syncthreads();

        int j = tid & 127, half = tid >> 7;
        float acc = half ? 0.f : (blat[j] + blf[j]);
        if (half == 0){
            #pragma unroll 4
            for (int i=0;i<512;i++) acc = fmaf(lat_s[i], Wlat[i*128+j], acc);
        } else {
            #pragma unroll 4
            for (int i=512;i<1024;i++) acc = fmaf(lat_s[i], Wlat[i*128+j], acc);
            for (int f=0;f<32;f++)     acc = fmaf(lat_s[1024+f], Wlf[f*128+j], acc);
        }
        part_s[half*128 + j] = acc;
        __syncthreads();
        if (tid < 128) kv_s[tid] = part_s[tid] + part_s[128+tid];
        __syncthreads();

        {
            const float* W  = half ? Wv : Wk;
            float o = half ? bv[j] : bk[j];
            #pragma unroll 4
            for (int i=0;i<128;i++) o = fmaf(kv_s[i], W[i*128+j], o);
            if (half == 0) g_kg[(b*NT+t)*128 + j] = o;
            else           vg_s[j] = o;
        }
        __syncthreads();

        for (int o2=tid;o2<512;o2+=256){
            int h = o2 >> 7, j2 = o2 & 127;
            float a = 0.f;
            #pragma unroll
            for (int d=0;d<32;d++) a = fmaf(vg_s[h*32+d], Wgo[(h*32+d)*128+j2], a);
            g_vgo[((size_t)b*25 + t*4 + h)*128 + j2] = a;
        }
        if (t==0){
            for (int j2=tid;j2<128;j2+=256) g_vgo[((size_t)b*25 + 24)*128 + j2] = bgo[j2];
        }
        return;
    }

    if (blockIdx.x == 96){
        // ======== weight/bias pack + consts ========
        float* W1t = sbuf;   // 4096: lng[i]*Wm1[i][j], i<64
        for (int e=tid;e<4096;e+=256) W1t[e] = lng[e>>6]*Wm1[e];
        __syncthreads();

        for (int e=tid;e<8192;e+=256){
            int k=e>>6, j=e&63;
            g_Wpack[k*328 + j]      = Wql[e];
            g_Wpack[k*328 + 64 + j] = Wnbr[128+e];
        }
        for (int e=tid;e<16384;e+=256){
            int k=e>>7, j=e&127;
            g_Wpack[k*328 + 128 + j] = Wqg[e];
        }
        // fused spW weight: Wnb' @ W1t  [128x64]
        for (int e=tid;e<8192;e+=256){
            int c=e>>6, j=e&63;
            float a = 0.f;
            #pragma unroll 4
            for (int i=0;i<64;i++) a = fmaf(Wnbr[128 + c*64 + i], W1t[i*64+j], a);
            g_Wpack[c*328 + 256 + j] = a;
        }
        // a0/a1 fused weights
        if (tid < 256){
            int k = tid & 127, which = tid >> 7;
            float a = 0.f;
            for (int i=0;i<64;i++) a = fmaf(Wql[k*64+i], Wnbr[which*64 + i], a);
            g_Wpack[k*328 + 320 + which] = a;
        }
        // zero pad cols 322..327
        if (tid < 128){
            for (int c=322;c<328;c++) g_Wpack[tid*328+c] = 0.f;
        }
        // biases
        if (tid < 64){
            g_bpack[tid]      = bql[tid];
            g_bpack[64+tid]   = bnbr[tid];
            float bf = 0.f;
            for (int i=0;i<64;i++) bf = fmaf(bnbr[i], W1t[i*64+tid], bf);
            g_bpack[256+tid] = bf;
        }
        if (tid < 128) g_bpack[128+tid] = bqg[tid];
        if (tid == 0){
            float a0=0.f, a1=0.f;
            for (int i=0;i<64;i++){ a0 = fmaf(bql[i], Wnbr[i], a0); a1 = fmaf(bql[i], Wnbr[64+i], a1); }
            g_bpack[320] = a0; g_bpack[321] = a1;
        }
        // consts
        if (tid < 64){
            int j = tid;
            float w0W=0.f, w1W=0.f, gcol=0.f, cadd=0.f;
            for (int i=0;i<192;i++){
                float w = Wm1[i*64+j];
                gcol += lng[i]*w;
                cadd += lnb[i]*w;
            }
            for (int i=0;i<64;i++){
                float w = lng[i]*Wm1[i*64+j];
                w0W += Wnbr[i]     * w;
                w1W += Wnbr[64+i]  * w;
            }
            g_cst[j]      = w0W;
            g_cst[64+j]   = w1W;
            g_cst[128+j]  = gcol;
            g_cst[192+j]  = cadd + bm1[j];
        }
        return;
    }

    // ======== query matrix build ========
    {
        int n0 = (blockIdx.x - 97) * 256;
        for (int e=tid;e<256*128;e+=256){
            int s = e>>7, k = e&127, n = n0 + s;
            if (n >= NS) break;
            g_q[n*128 + k] = (k<96) ? pos[n*96+k] : femb[fid[n]*32 + (k-96)];
        }
    }
}

// ------------------------- kGEMM: [4760x128]@[128x322] (y<6) | vgo folds (y==6) ----
__global__ void __launch_bounds__(256,1) kGEMM(const float* __restrict__ lng, const float* __restrict__ Wm1){
    extern __shared__ float sm[];
    int tid = threadIdx.x;

    if (blockIdx.y == 6){
        // ======== vgo folds: vgoW, gram, sumv ========
        float* w1bT = sm;   // 64*132 = 8448
        for (int e=tid;e<8192;e+=256){ int c=e>>6, j=e&63; w1bT[j*132+c] = lng[64+c]*Wm1[4096+e]; }
        __syncthreads();

        int lane = tid & 31, c4 = lane*4;
        int gw = blockIdx.x*8 + (tid>>5);   // 75 blocks x 8 warps = 600

        for (int task=gw; task<36000; task+=600){
            int b = task/2250, tt = task - b*2250;
            if (tt < 1600){
                int i = tt >> 6, j = tt & 63;
                float4 a = *(const float4*)(g_vgo + ((size_t)b*25+i)*128 + c4);
                float4 w = *(const float4*)(w1bT + j*132 + c4);
                float v = a.x*w.x + a.y*w.y + a.z*w.z + a.w*w.w;
                v = wsum(v);
                if (lane==0) g_vgoW[(b*25+i)*64 + j] = v;
            } else if (tt < 2225){
                int p = tt - 1600, i1 = p/25, i2 = p - i1*25;
                float4 a = *(const float4*)(g_vgo + ((size_t)b*25+i1)*128 + c4);
                float4 c = *(const float4*)(g_vgo + ((size_t)b*25+i2)*128 + c4);
                float v = a.x*c.x + a.y*c.y + a.z*c.z + a.w*c.w;
                v = wsum(v);
                if (lane==0) g_gram[b*625 + p] = v;
            } else {
                int i = tt - 2225;
                float4 a = *(const float4*)(g_vgo + ((size_t)b*25+i)*128 + c4);
                float v = a.x + a.y + a.z + a.w;
                v = wsum(v);
                if (lane==0) g_sumv[b*25 + i] = v;
            }
        }
        return;
    }

    // ======== GEMM tile ========
    float* AT = sm;          // 128*68 = 8704
    float* Ws = sm + 8704;   // 128*64 = 8192
    int n0 = blockIdx.x * 64;
    int c0 = blockIdx.y * 64;

    for (int e=tid;e<64*128;e+=256){
        int s = e>>7, k = e&127, n = n0+s;
        AT[k*68 + s] = (n<NS) ? g_q[n*128 + k] : 0.f;
    }
    for (int e=tid;e<8192;e+=256){
        int k = e>>6, cc = e&63;
        Ws[e] = g_Wpack[k*328 + c0 + cc];   // cols 322..327 are zero-padded
    }
    __syncthreads();

    int cg = tid & 15, sg = tid >> 4;
    const float4* Wb = (const float4*)Ws + cg;    // stride 16 float4
    const float4* Ab = (const float4*)AT + sg;    // stride 17 float4

    float acc[4][4];
    #pragma unroll
    for (int s=0;s<4;s++){ acc[s][0]=0.f; acc[s][1]=0.f; acc[s][2]=0.f; acc[s][3]=0.f; }

    #pragma unroll 4
    for (int k=0;k<128;k++){
        float4 w = Wb[k*16];
        float4 a = Ab[k*17];
        float av[4] = {a.x, a.y, a.z, a.w};
        #pragma unroll
        for (int s=0;s<4;s++){
            acc[s][0] = fmaf(av[s], w.x, acc[s][0]);
            acc[s][1] = fmaf(av[s], w.y, acc[s][1]);
            acc[s][2] = fmaf(av[s], w.z, acc[s][2]);
            acc[s][3] = fmaf(av[s], w.w, acc[s][3]);
        }
    }

    #pragma unroll
    for (int s=0;s<4;s++){
        int n = n0 + sg*4 + s;
        if (n >= NS) continue;
        #pragma unroll
        for (int u=0;u<4;u++){
            int c = c0 + cg*4 + u;
            if (c >= 322) continue;
            float v = acc[s][u] + g_bpack[c];
            if (c < 64)        g_ql [n*64 + c]        = v;
            else if (c < 128)  g_sp [n*64 + (c-64)]   = v;
            else if (c < 256)  g_qg [n*128 + (c-128)] = v;
            else if (c < 320)  g_spW[n*64 + (c-256)]  = v;
            else if (c == 320) g_a0[n] = v;
            else               g_a1[n] = v;
        }
    }
}

// ------------------------- kFH: per-(n,b) global logits + softmax + Pg/sumg/sumg2 ----
__global__ void __launch_bounds__(128,1) kFH(){
    __shared__ float Ks[24*32];       // rows h*6+t
    __shared__ float vgoW_s[25*64];
    __shared__ float gram_s[25*28];   // padded rows
    __shared__ float sumv_s[25];
    int b = blockIdx.y;
    int n0 = blockIdx.x * 128;
    int tid = threadIdx.x;

    for (int e=tid;e<768;e+=128){
        int r=e>>5, k=e&31, h=r/6, t=r%6;
        Ks[e] = g_kg[(b*6+t)*128 + h*32 + k];
    }
    for (int e=tid;e<1600;e+=128) vgoW_s[e] = g_vgoW[b*1600 + e];
    for (int e=tid;e<625;e+=128){ int i=e/25, j=e-i*25; gram_s[i*28+j] = g_gram[b*625 + e]; }
    if (tid < 25) sumv_s[tid] = g_sumv[b*25 + tid];
    __syncthreads();

    int n = n0 + tid;
    bool valid = (n < NS);
    int nr = valid ? n : (NS-1);
    const float4* qrow = (const float4*)(g_qg + (size_t)nr*128);

    float ga[24];
    const float scale = 0.17677669529663687f;
    #pragma unroll
    for (int h=0;h<4;h++){
        float4 q[8];
        #pragma unroll
        for (int i=0;i<8;i++) q[i] = qrow[h*8+i];
        float lg[6];
        #pragma unroll
        for (int t=0;t<6;t++){
            const float4* kr = (const float4*)(Ks + (h*6+t)*32);
            float a = 0.f;
            #pragma unroll
            for (int i=0;i<8;i++){
                float4 kv = kr[i];
                a = fmaf(q[i].x, kv.x, a);
                a = fmaf(q[i].y, kv.y, a);
                a = fmaf(q[i].z, kv.z, a);
                a = fmaf(q[i].w, kv.w, a);
            }
            lg[t] = a;
        }
        float m = lg[0];
        #pragma unroll
        for (int t=1;t<6;t++) m = fmaxf(m, lg[t]);
        float den = 0.f, ex[6];
        #pragma unroll
        for (int t=0;t<6;t++){ ex[t] = __expf((lg[t]-m)*scale); den += ex[t]; }
        float inv = 1.f/den;
        #pragma unroll
        for (int t=0;t<6;t++) ga[t*4+h] = ex[t]*inv;
    }

    // Pg = vgoW[24] + sum_i ga[i]*vgoW[i]
    float4 Pg[16];
    {
        const float4* w24 = (const float4*)(vgoW_s + 24*64);
        #pragma unroll
        for (int j=0;j<16;j++) Pg[j] = w24[j];
    }
    #pragma unroll
    for (int i=0;i<24;i++){
        float g = ga[i];
        const float4* wr = (const float4*)(vgoW_s + i*64);
        #pragma unroll
        for (int j=0;j<16;j++){
            float4 w = wr[j];
            Pg[j].x = fmaf(g, w.x, Pg[j].x);
            Pg[j].y = fmaf(g, w.y, Pg[j].y);
            Pg[j].z = fmaf(g, w.z, Pg[j].z);
            Pg[j].w = fmaf(g, w.w, Pg[j].w);
        }
    }
    // sumg
    float sumg = sumv_s[24];
    #pragma unroll
    for (int i=0;i<24;i++) sumg = fmaf(ga[i], sumv_s[i], sumg);
    // sumg2 = gaE . Gram . gaE
    float sumg2 = 0.f;
    #pragma unroll
    for (int i=0;i<25;i++){
        const float4* gr = (const float4*)(gram_s + i*28);
        float ti = gram_s[i*28 + 24];     // j=24 coefficient 1
        #pragma unroll
        for (int j4=0;j4<6;j4++){
            float4 gv = gr[j4];
            ti = fmaf(gv.x, ga[j4*4+0], ti);
            ti = fmaf(gv.y, ga[j4*4+1], ti);
            ti = fmaf(gv.z, ga[j4*4+2], ti);
            ti = fmaf(gv.w, ga[j4*4+3], ti);
        }
        float gi = (i<24) ? ga[i] : 1.f;
        sumg2 = fmaf(gi, ti, sumg2);
    }

    if (valid){
        float4* dst = (float4*)(g_pg + ((size_t)n*16 + b)*68);
        #pragma unroll
        for (int j=0;j<16;j++) dst[j] = Pg[j];
        float* d2 = (float*)(dst + 16);
        d2[0] = sumg; d2[1] = sumg2;
    }
}

// ------------------------- kG: fused main (one sensor per warp) -------------------------
__global__ void __launch_bounds__(256,1) kG(
    const float* __restrict__ xf, const int* __restrict__ mask, const int* __restrict__ knn,
    const float* __restrict__ Wnbr, const float* __restrict__ Wm2, const float* __restrict__ bm2,
    float* __restrict__ out)
{
    __shared__ float cst[448];
    int tid = threadIdx.x;
    if (tid < 128) cst[tid] = Wnbr[tid];
    cst[128+tid] = g_cst[tid];
    if (tid < 64) cst[384+tid] = Wm2[tid];
    __syncthreads();
    const float* w0_s  = cst;
    const float* w1_s  = cst + 64;
    const float* w0W_s = cst + 128;
    const float* w1W_s = cst + 192;
    const float* gcol_s= cst + 256;
    const float* cadd_s= cst + 320;
    const float* wm2_s = cst + 384;

    const unsigned FULL = 0xffffffffu;
    int wid = tid >> 5, lane = tid & 31;
    float bm2v = bm2[0];

    int n = blockIdx.x*8 + wid;
    if (n >= NS) return;

    int kj = 0;
    if (lane < 16) kj = knn[n*16 + lane];
    float a0 = g_a0[n], a1 = g_a1[n];
    float ql0 = g_ql[n*64 + lane], ql1 = g_ql[n*64 + 32 + lane];
    float rsp0[16], rsp1[16], rw0[16], rw1[16];
    #pragma unroll
    for (int k=0;k<16;k++){
        int j = __shfl_sync(FULL, kj, k);
        rsp0[k] = g_sp[j*64 + lane];
        rsp1[k] = g_sp[j*64 + 32 + lane];
        rw0[k]  = g_spW[j*64 + lane];
        rw1[k]  = g_spW[j*64 + 32 + lane];
    }
    float Sreg = 0.f;
    #pragma unroll
    for (int k0=0;k0<16;k0+=4){
        float p[4];
        #pragma unroll
        for (int u=0;u<4;u++) p[u] = fmaf(rsp0[k0+u], ql0, rsp1[k0+u]*ql1);
        wsumv<4>(p);
        if (lane == k0)   Sreg = p[0];
        if (lane == k0+1) Sreg = p[1];
        if (lane == k0+2) Sreg = p[2];
        if (lane == k0+3) Sreg = p[3];
    }

    for (int b=0;b<16;b++){
        int mn = mask[b*NS + n];
        const float* pg = g_pg + ((size_t)n*16 + b)*68;
        float Pg0  = pg[lane];
        float Pg1  = pg[32+lane];
        float sumg = pg[64];
        float sumg2= pg[65];

        // ---- local attention ----
        float x0 = 0.f, x1 = 0.f, logit = -CUDART_INF_F;
        if (lane < 16){
            float2 xv = *(const float2*)(xf + (size_t)(b*NS + kj)*2);
            x0 = xv.x; x1 = xv.y;
            int mk = mask[b*NS + kj];
            logit = (mk != 0) ? -10000.f : (Sreg + x0*a0 + x1*a1)*0.125f;
        }
        float mx  = wmax(logit);
        float red3[3];
        float e = (lane < 16) ? __expf(logit - mx) : 0.f;
        red3[0] = e; red3[1] = e*x0; red3[2] = e*x1;
        wsumv<3>(red3);
        float inv = 1.f/red3[0];
        float attn = e*inv;
        float alpha = red3[1]*inv, beta = red3[2]*inv;

        float L0 = alpha*w0_s[lane]      + beta*w1_s[lane];
        float L1 = alpha*w0_s[32+lane]   + beta*w1_s[32+lane];
        float P0 = alpha*w0W_s[lane]     + beta*w1W_s[lane];
        float P1 = alpha*w0W_s[32+lane]  + beta*w1W_s[32+lane];
        #pragma unroll
        for (int k=0;k<16;k++){
            float ak = __shfl_sync(FULL, attn, k);
            L0 = fmaf(ak, rsp0[k], L0);
            L1 = fmaf(ak, rsp1[k], L1);
            P0 = fmaf(ak, rw0[k],  P0);
            P1 = fmaf(ak, rw1[k],  P1);
        }
        float redL[2];
        redL[0] = L0 + L1;
        redL[1] = L0*L0 + L1*L1;
        wsumv<2>(redL);
        float sL = redL[0], sL2 = redL[1];

        // ---- LN + MLP fold ----
        float mean = (sL + sumg)*(1.f/192.f);
        float var  = (sL2 + sumg2)*(1.f/192.f) - mean*mean;
        float rstd = rsqrtf(var + 1e-5f);
        float h0 = fmaf(rstd, (P0+Pg0) - mean*gcol_s[lane],    cadd_s[lane]);
        float h1 = fmaf(rstd, (P1+Pg1) - mean*gcol_s[32+lane], cadd_s[32+lane]);
        float gelu0 = 0.5f*h0*(1.f + erff(h0*0.70710678118654752f));
        float gelu1 = 0.5f*h1*(1.f + erff(h1*0.70710678118654752f));
        float pr = wsum(fmaf(gelu0, wm2_s[lane], gelu1*wm2_s[32+lane]));
        if (lane == 0){
            out[b*NS + n] = mn ? (pr + bm2v) : 0.f;
        }
    }
}

// ------------------------- launch -------------------------
extern "C" void kernel_launch(void* const* d_in, const int* in_sizes, int n_in,
                              void* d_out, int out_size){
    const float* xf    = (const float*)d_in[0];
    const float* latent= (const float*)d_in[1];
    const float* pos   = (const float*)d_in[2];
    const float* femb  = (const float*)d_in[3];
    const float* Wnbr  = (const float*)d_in[4];
    const float* bnbr  = (const float*)d_in[5];
    const float* Wql   = (const float*)d_in[6];
    const float* bql   = (const float*)d_in[7];
    const float* Wlat  = (const float*)d_in[8];
    const float* blat  = (const float*)d_in[9];
    const float* Wlf   = (const float*)d_in[10];
    const float* blf   = (const float*)d_in[11];
    const float* Wqg   = (const float*)d_in[12];
    const float* bqg   = (const float*)d_in[13];
    const float* Wk    = (const float*)d_in[14];
    const float* bk    = (const float*)d_in[15];
    const float* Wv    = (const float*)d_in[16];
    const float* bv    = (const float*)d_in[17];
    const float* Wgo   = (const float*)d_in[18];
    const float* bgo   = (const float*)d_in[19];
    const float* lng   = (const float*)d_in[20];
    const float* lnb   = (const float*)d_in[21];
    const float* Wm1   = (const float*)d_in[22];
    const float* bm1   = (const float*)d_in[23];
    const float* Wm2   = (const float*)d_in[24];
    const float* bm2   = (const float*)d_in[25];
    const int* mask    = (const int*)d_in[26];
    const int* knn     = (const int*)d_in[27];
    const int* fid     = (const int*)d_in[28];
    float* out = (float*)d_out;

    cudaFuncSetAttribute(kGEMM, cudaFuncAttributeMaxDynamicSharedMemorySize, 16896*4);

    kPrep<<<116,256>>>(pos, femb, fid, Wnbr, bnbr, Wql, bql, Wqg, bqg, lng, lnb, Wm1, bm1,
                       latent, Wlat, blat, Wlf, blf, Wk, bk, Wv, bv, Wgo, bgo);
    kGEMM<<<dim3(75,7),256,16896*4>>>(lng, Wm1);
    kFH<<<dim3(38,16),128>>>();
    kG<<<595,256>>>(xf, mask, knn, Wnbr, Wm2, bm2, out);
}

// round 7
// speedup vs baseline: 1.1169x; 1.0092x over previous
#include <cuda_runtime.h>
#include <math.h>
#include <math_constants.h>

#define NS 4760
#define KNN 16
#define NB 16
#define NT 6

// ------------------------- device scratch -------------------------
__device__ float g_q  [NS*128];      // query features
__device__ float g_Wpack[128*328];   // packed fused weights
__device__ float g_bpack[328];       // packed biases
__device__ float g_ql [NS*64];
__device__ float g_sp [NS*64];
__device__ float g_spW[NS*64];
__device__ float g_qg [NS*128];
__device__ float g_a0 [NS];
__device__ float g_a1 [NS];
__device__ float g_kg [NB*NT*128];
__device__ float g_vgo [NB*25*128];
__device__ float g_vgoW[NB*25*64];
__device__ float g_sumv[NB*25];
__device__ float g_gram[NB*25*25];
__device__ float g_pg  [(size_t)NB*NS*68];   // [b][n][68]: Pg[64], sumg, sumg2, pad
__device__ float g_cst [256];   // [w0W(64) w1W(64) gcol(64) cadd(64)]

__device__ __forceinline__ float wsum(float v){
    #pragma unroll
    for (int o=16;o;o>>=1) v += __shfl_xor_sync(0xffffffffu, v, o);
    return v;
}
__device__ __forceinline__ float wmax(float v){
    #pragma unroll
    for (int o=16;o;o>>=1) v = fmaxf(v, __shfl_xor_sync(0xffffffffu, v, o));
    return v;
}
template<int N>
__device__ __forceinline__ void wsumv(float* v){
    #pragma unroll
    for (int o=16;o;o>>=1){
        #pragma unroll
        for (int i=0;i<N;i++) v[i] += __shfl_xor_sync(0xffffffffu, v[i], o);
    }
}

// ------------------------- kPrep: latent path (0-95) | weight pack (96) | q build (97+) ----
__global__ void __launch_bounds__(256,1) kPrep(
    const float* __restrict__ pos, const float* __restrict__ femb, const int* __restrict__ fid,
    const float* __restrict__ Wnbr, const float* __restrict__ bnbr,
    const float* __restrict__ Wql,  const float* __restrict__ bql,
    const float* __restrict__ Wqg,  const float* __restrict__ bqg,
    const float* __restrict__ lng,  const float* __restrict__ lnb,
    const float* __restrict__ Wm1,  const float* __restrict__ bm1,
    const float* __restrict__ latent,
    const float* __restrict__ Wlat, const float* __restrict__ blat,
    const float* __restrict__ Wlf,  const float* __restrict__ blf,
    const float* __restrict__ Wk,   const float* __restrict__ bk,
    const float* __restrict__ Wv,   const float* __restrict__ bv,
    const float* __restrict__ Wgo,  const float* __restrict__ bgo)
{
    __shared__ float sbuf[4608];
    int tid = threadIdx.x;

    if (blockIdx.x < 96){
        // ======== latent path ========
        float* lat_s  = sbuf;           // 1056
        float* part_s = sbuf + 1056;    // 256
        float* kv_s   = sbuf + 1312;    // 128
        float* vg_s   = sbuf + 1440;    // 128
        int idx = blockIdx.x;
        int t = idx % NT, b = idx / NT;
        for (int e=tid;e<1024;e+=256) lat_s[e] = latent[((size_t)b*NT+t)*1024 + e];
        if (tid<32) lat_s[1024+tid] = femb[t*32+tid];
        __syncthreads();

        int j = tid & 127, half = tid >> 7;
        float acc = half ? 0.f : (blat[j] + blf[j]);
        if (half == 0){
            #pragma unroll 4
            for (int i=0;i<512;i++) acc = fmaf(lat_s[i], Wlat[i*128+j], acc);
        } else {
            #pragma unroll 4
            for (int i=512;i<1024;i++) acc = fmaf(lat_s[i], Wlat[i*128+j], acc);
            for (int f=0;f<32;f++)     acc = fmaf(lat_s[1024+f], Wlf[f*128+j], acc);
        }
        part_s[half*128 + j] = acc;
        __syncthreads();
        if (tid < 128) kv_s[tid] = part_s[tid] + part_s[128+tid];
        __syncthreads();

        {
            const float* W  = half ? Wv : Wk;
            float o = half ? bv[j] : bk[j];
            #pragma unroll 4
            for (int i=0;i<128;i++) o = fmaf(kv_s[i], W[i*128+j], o);
            if (half == 0) g_kg[(b*NT+t)*128 + j] = o;
            else           vg_s[j] = o;
        }
        __syncthreads();

        for (int o2=tid;o2<512;o2+=256){
            int h = o2 >> 7, j2 = o2 & 127;
            float a = 0.f;
            #pragma unroll
            for (int d=0;d<32;d++) a = fmaf(vg_s[h*32+d], Wgo[(h*32+d)*128+j2], a);
            g_vgo[((size_t)b*25 + t*4 + h)*128 + j2] = a;
        }
        if (t==0){
            for (int j2=tid;j2<128;j2+=256) g_vgo[((size_t)b*25 + 24)*128 + j2] = bgo[j2];
        }
        return;
    }

    if (blockIdx.x == 96){
        // ======== weight/bias pack + consts ========
        float* W1t = sbuf;   // 4096: lng[i]*Wm1[i][j], i<64
        for (int e=tid;e<4096;e+=256) W1t[e] = lng[e>>6]*Wm1[e];
        __syncthreads();

        for (int e=tid;e<8192;e+=256){
            int k=e>>6, j=e&63;
            g_Wpack[k*328 + j]      = Wql[e];
            g_Wpack[k*328 + 64 + j] = Wnbr[128+e];
        }
        for (int e=tid;e<16384;e+=256){
            int k=e>>7, j=e&127;
            g_Wpack[k*328 + 128 + j] = Wqg[e];
        }
        // fused spW weight: Wnb' @ W1t  [128x64]
        for (int e=tid;e<8192;e+=256){
            int c=e>>6, j=e&63;
            float a = 0.f;
            #pragma unroll 4
            for (int i=0;i<64;i++) a = fmaf(Wnbr[128 + c*64 + i], W1t[i*64+j], a);
            g_Wpack[c*328 + 256 + j] = a;
        }
        // a0/a1 fused weights
        if (tid < 256){
            int k = tid & 127, which = tid >> 7;
            float a = 0.f;
            for (int i=0;i<64;i++) a = fmaf(Wql[k*64+i], Wnbr[which*64 + i], a);
            g_Wpack[k*328 + 320 + which] = a;
        }
        // zero pad cols 322..327
        if (tid < 128){
            for (int c=322;c<328;c++) g_Wpack[tid*328+c] = 0.f;
        }
        // biases
        if (tid < 64){
            g_bpack[tid]      = bql[tid];
            g_bpack[64+tid]   = bnbr[tid];
            float bf = 0.f;
            for (int i=0;i<64;i++) bf = fmaf(bnbr[i], W1t[i*64+tid], bf);
            g_bpack[256+tid] = bf;
        }
        if (tid < 128) g_bpack[128+tid] = bqg[tid];
        if (tid == 0){
            float a0=0.f, a1=0.f;
            for (int i=0;i<64;i++){ a0 = fmaf(bql[i], Wnbr[i], a0); a1 = fmaf(bql[i], Wnbr[64+i], a1); }
            g_bpack[320] = a0; g_bpack[321] = a1;
        }
        // consts
        if (tid < 64){
            int j = tid;
            float w0W=0.f, w1W=0.f, gcol=0.f, cadd=0.f;
            for (int i=0;i<192;i++){
                float w = Wm1[i*64+j];
                gcol += lng[i]*w;
                cadd += lnb[i]*w;
            }
            for (int i=0;i<64;i++){
                float w = lng[i]*Wm1[i*64+j];
                w0W += Wnbr[i]     * w;
                w1W += Wnbr[64+i]  * w;
            }
            g_cst[j]      = w0W;
            g_cst[64+j]   = w1W;
            g_cst[128+j]  = gcol;
            g_cst[192+j]  = cadd + bm1[j];
        }
        return;
    }

    // ======== query matrix build ========
    {
        int n0 = (blockIdx.x - 97) * 256;
        for (int e=tid;e<256*128;e+=256){
            int s = e>>7, k = e&127, n = n0 + s;
            if (n >= NS) break;
            g_q[n*128 + k] = (k<96) ? pos[n*96+k] : femb[fid[n]*32 + (k-96)];
        }
    }
}

// ------------------------- kGEMM: [4760x128]@[128x322] (y<6) | vgo folds (y==6) ----
__global__ void __launch_bounds__(256,1) kGEMM(const float* __restrict__ lng, const float* __restrict__ Wm1){
    extern __shared__ float sm[];
    int tid = threadIdx.x;

    if (blockIdx.y == 6){
        // ======== vgo folds: vgoW, gram, sumv ========
        float* w1bT = sm;   // 64*132 = 8448
        for (int e=tid;e<8192;e+=256){ int c=e>>6, j=e&63; w1bT[j*132+c] = lng[64+c]*Wm1[4096+e]; }
        __syncthreads();

        int lane = tid & 31, c4 = lane*4;
        int gw = blockIdx.x*8 + (tid>>5);   // 75 blocks x 8 warps = 600

        for (int task=gw; task<36000; task+=600){
            int b = task/2250, tt = task - b*2250;
            if (tt < 1600){
                int i = tt >> 6, j = tt & 63;
                float4 a = *(const float4*)(g_vgo + ((size_t)b*25+i)*128 + c4);
                float4 w = *(const float4*)(w1bT + j*132 + c4);
                float v = a.x*w.x + a.y*w.y + a.z*w.z + a.w*w.w;
                v = wsum(v);
                if (lane==0) g_vgoW[(b*25+i)*64 + j] = v;
            } else if (tt < 2225){
                int p = tt - 1600, i1 = p/25, i2 = p - i1*25;
                float4 a = *(const float4*)(g_vgo + ((size_t)b*25+i1)*128 + c4);
                float4 c = *(const float4*)(g_vgo + ((size_t)b*25+i2)*128 + c4);
                float v = a.x*c.x + a.y*c.y + a.z*c.z + a.w*c.w;
                v = wsum(v);
                if (lane==0) g_gram[b*625 + p] = v;
            } else {
                int i = tt - 2225;
                float4 a = *(const float4*)(g_vgo + ((size_t)b*25+i)*128 + c4);
                float v = a.x + a.y + a.z + a.w;
                v = wsum(v);
                if (lane==0) g_sumv[b*25 + i] = v;
            }
        }
        return;
    }

    // ======== GEMM tile ========
    float* AT = sm;          // 128*68 = 8704
    float* Ws = sm + 8704;   // 128*64 = 8192
    int n0 = blockIdx.x * 64;
    int c0 = blockIdx.y * 64;

    for (int e=tid;e<64*128;e+=256){
        int s = e>>7, k = e&127, n = n0+s;
        AT[k*68 + s] = (n<NS) ? g_q[n*128 + k] : 0.f;
    }
    for (int e=tid;e<8192;e+=256){
        int k = e>>6, cc = e&63;
        Ws[e] = g_Wpack[k*328 + c0 + cc];   // cols 322..327 are zero-padded
    }
    __syncthreads();

    int cg = tid & 15, sg = tid >> 4;
    const float4* Wb = (const float4*)Ws + cg;    // stride 16 float4
    const float4* Ab = (const float4*)AT + sg;    // stride 17 float4

    float acc[4][4];
    #pragma unroll
    for (int s=0;s<4;s++){ acc[s][0]=0.f; acc[s][1]=0.f; acc[s][2]=0.f; acc[s][3]=0.f; }

    #pragma unroll 4
    for (int k=0;k<128;k++){
        float4 w = Wb[k*16];
        float4 a = Ab[k*17];
        float av[4] = {a.x, a.y, a.z, a.w};
        #pragma unroll
        for (int s=0;s<4;s++){
            acc[s][0] = fmaf(av[s], w.x, acc[s][0]);
            acc[s][1] = fmaf(av[s], w.y, acc[s][1]);
            acc[s][2] = fmaf(av[s], w.z, acc[s][2]);
            acc[s][3] = fmaf(av[s], w.w, acc[s][3]);
        }
    }

    #pragma unroll
    for (int s=0;s<4;s++){
        int n = n0 + sg*4 + s;
        if (n >= NS) continue;
        #pragma unroll
        for (int u=0;u<4;u++){
            int c = c0 + cg*4 + u;
            if (c >= 322) continue;
            float v = acc[s][u] + g_bpack[c];
            if (c < 64)        g_ql [n*64 + c]        = v;
            else if (c < 128)  g_sp [n*64 + (c-64)]   = v;
            else if (c < 256)  g_qg [n*128 + (c-128)] = v;
            else if (c < 320)  g_spW[n*64 + (c-256)]  = v;
            else if (c == 320) g_a0[n] = v;
            else               g_a1[n] = v;
        }
    }
}

// ------------------------- kFH: per-(n,b) global softmax + Pg/sumg/sumg2 ----
// Block: 128 sensors, one b. qg staged per-h via smem; output flushed via smem.
__global__ void __launch_bounds__(128,1) kFH(){
    __shared__ float buf[128*69];     // union: qs [s*33+k] during logits; out [s*69+j] at flush
    __shared__ float Ks[24*32];       // rows h*6+t
    __shared__ float vgoW_s[25*64];
    __shared__ float gram_s[25*28];
    __shared__ float sumv_s[32];
    int b = blockIdx.y;
    int n0 = blockIdx.x * 128;
    int tid = threadIdx.x;

    for (int e=tid;e<768;e+=128){
        int r=e>>5, k=e&31, h=r/6, t=r%6;
        Ks[e] = g_kg[(b*6+t)*128 + h*32 + k];
    }
    for (int e=tid;e<1600;e+=128) vgoW_s[e] = g_vgoW[b*1600 + e];
    for (int e=tid;e<625;e+=128){ int i=e/25, j=e-i*25; gram_s[i*28+j] = g_gram[b*625 + e]; }
    if (tid < 25) sumv_s[tid] = g_sumv[b*25 + tid];

    float ga[24];
    const float scale = 0.17677669529663687f;
    int nclamp = (n0 + tid < NS) ? (n0 + tid) : (NS-1);

    #pragma unroll
    for (int h=0;h<4;h++){
        __syncthreads();
        // stage qg[:, h*32 : h*32+32] for this sensor tile (coalesced)
        for (int e=tid;e<4096;e+=128){
            int s=e>>5, k=e&31;
            int nr = (n0+s < NS) ? (n0+s) : (NS-1);
            buf[s*33+k] = g_qg[nr*128 + h*32 + k];
        }
        __syncthreads();

        float q[32];
        #pragma unroll
        for (int k=0;k<32;k++) q[k] = buf[tid*33 + k];

        float lg[6];
        #pragma unroll
        for (int t=0;t<6;t++){
            const float* kr = Ks + (h*6+t)*32;
            float a = 0.f;
            #pragma unroll
            for (int k=0;k<32;k++) a = fmaf(q[k], kr[k], a);
            lg[t] = a;
        }
        float m = lg[0];
        #pragma unroll
        for (int t=1;t<6;t++) m = fmaxf(m, lg[t]);
        float den = 0.f, ex[6];
        #pragma unroll
        for (int t=0;t<6;t++){ ex[t] = __expf((lg[t]-m)*scale); den += ex[t]; }
        float inv = 1.f/den;
        #pragma unroll
        for (int t=0;t<6;t++) ga[t*4+h] = ex[t]*inv;
    }
    (void)nclamp;

    // Pg = vgoW[24] + sum_i ga[i]*vgoW[i]   (broadcast LDS, conflict-free)
    float4 Pg[16];
    {
        const float4* w24 = (const float4*)(vgoW_s + 24*64);
        #pragma unroll
        for (int j=0;j<16;j++) Pg[j] = w24[j];
    }
    #pragma unroll
    for (int i=0;i<24;i++){
        float g = ga[i];
        const float4* wr = (const float4*)(vgoW_s + i*64);
        #pragma unroll
        for (int j=0;j<16;j++){
            float4 w = wr[j];
            Pg[j].x = fmaf(g, w.x, Pg[j].x);
            Pg[j].y = fmaf(g, w.y, Pg[j].y);
            Pg[j].z = fmaf(g, w.z, Pg[j].z);
            Pg[j].w = fmaf(g, w.w, Pg[j].w);
        }
    }
    // sumg
    float sumg = sumv_s[24];
    #pragma unroll
    for (int i=0;i<24;i++) sumg = fmaf(ga[i], sumv_s[i], sumg);
    // sumg2 = gaE . Gram . gaE
    float sumg2 = 0.f;
    #pragma unroll
    for (int i=0;i<25;i++){
        const float4* gr = (const float4*)(gram_s + i*28);
        float ti = gram_s[i*28 + 24];
        #pragma unroll
        for (int j4=0;j4<6;j4++){
            float4 gv = gr[j4];
            ti = fmaf(gv.x, ga[j4*4+0], ti);
            ti = fmaf(gv.y, ga[j4*4+1], ti);
            ti = fmaf(gv.z, ga[j4*4+2], ti);
            ti = fmaf(gv.w, ga[j4*4+3], ti);
        }
        float gi = (i<24) ? ga[i] : 1.f;
        sumg2 = fmaf(gi, ti, sumg2);
    }

    // stage to smem (bank-safe: stride 69, gcd(5,32)=1) then flush coalesced
    __syncthreads();
    {
        float* o = buf + tid*69;
        #pragma unroll
        for (int j=0;j<16;j++){
            o[j*4+0] = Pg[j].x; o[j*4+1] = Pg[j].y; o[j*4+2] = Pg[j].z; o[j*4+3] = Pg[j].w;
        }
        o[64] = sumg; o[65] = sumg2; o[66] = 0.f; o[67] = 0.f;
    }
    __syncthreads();
    int rows = NS - n0; if (rows > 128) rows = 128;
    float* dst = g_pg + ((size_t)b*NS + n0)*68;
    for (int e=tid; e<rows*68; e+=128){
        int s = e/68, j = e - s*68;
        dst[(size_t)s*68 + j] = buf[s*69 + j];
    }
}

// ------------------------- kG: fused main (one sensor per warp) -------------------------
__global__ void __launch_bounds__(256,1) kG(
    const float* __restrict__ xf, const int* __restrict__ mask, const int* __restrict__ knn,
    const float* __restrict__ Wnbr, const float* __restrict__ Wm2, const float* __restrict__ bm2,
    float* __restrict__ out)
{
    __shared__ float cst[448];
    int tid = threadIdx.x;
    if (tid < 128) cst[tid] = Wnbr[tid];
    cst[128+tid] = g_cst[tid & 255];
    if (tid < 64) cst[384+tid] = Wm2[tid];
    __syncthreads();
    const float* w0_s  = cst;
    const float* w1_s  = cst + 64;
    const float* w0W_s = cst + 128;
    const float* w1W_s = cst + 192;
    const float* gcol_s= cst + 256;
    const float* cadd_s= cst + 320;
    const float* wm2_s = cst + 384;

    const unsigned FULL = 0xffffffffu;
    int wid = tid >> 5, lane = tid & 31;
    float bm2v = bm2[0];

    int n = blockIdx.x*8 + wid;
    if (n >= NS) return;

    int kj = 0;
    if (lane < 16) kj = knn[n*16 + lane];
    float a0 = g_a0[n], a1 = g_a1[n];
    float ql0 = g_ql[n*64 + lane], ql1 = g_ql[n*64 + 32 + lane];
    float rsp0[16], rsp1[16], rw0[16], rw1[16];
    #pragma unroll
    for (int k=0;k<16;k++){
        int j = __shfl_sync(FULL, kj, k);
        rsp0[k] = g_sp[j*64 + lane];
        rsp1[k] = g_sp[j*64 + 32 + lane];
        rw0[k]  = g_spW[j*64 + lane];
        rw1[k]  = g_spW[j*64 + 32 + lane];
    }
    float Sreg = 0.f;
    #pragma unroll
    for (int k0=0;k0<16;k0+=4){
        float p[4];
        #pragma unroll
        for (int u=0;u<4;u++) p[u] = fmaf(rsp0[k0+u], ql0, rsp1[k0+u]*ql1);
        wsumv<4>(p);
        if (lane == k0)   Sreg = p[0];
        if (lane == k0+1) Sreg = p[1];
        if (lane == k0+2) Sreg = p[2];
        if (lane == k0+3) Sreg = p[3];
    }

    for (int b=0;b<16;b++){
        int mn = mask[b*NS + n];
        const float* pg = g_pg + ((size_t)b*NS + n)*68;
        float Pg0  = pg[lane];
        float Pg1  = pg[32+lane];
        float sumg = pg[64];
        float sumg2= pg[65];

        // ---- local attention ----
        float x0 = 0.f, x1 = 0.f, logit = -CUDART_INF_F;
        if (lane < 16){
            float2 xv = *(const float2*)(xf + (size_t)(b*NS + kj)*2);
            x0 = xv.x; x1 = xv.y;
            int mk = mask[b*NS + kj];
            logit = (mk != 0) ? -10000.f : (Sreg + x0*a0 + x1*a1)*0.125f;
        }
        float mx  = wmax(logit);
        float red3[3];
        float e = (lane < 16) ? __expf(logit - mx) : 0.f;
        red3[0] = e; red3[1] = e*x0; red3[2] = e*x1;
        wsumv<3>(red3);
        float inv = 1.f/red3[0];
        float attn = e*inv;
        float alpha = red3[1]*inv, beta = red3[2]*inv;

        float L0 = alpha*w0_s[lane]      + beta*w1_s[lane];
        float L1 = alpha*w0_s[32+lane]   + beta*w1_s[32+lane];
        float P0 = alpha*w0W_s[lane]     + beta*w1W_s[lane];
        float P1 = alpha*w0W_s[32+lane]  + beta*w1W_s[32+lane];
        #pragma unroll
        for (int k=0;k<16;k++){
            float ak = __shfl_sync(FULL, attn, k);
            L0 = fmaf(ak, rsp0[k], L0);
            L1 = fmaf(ak, rsp1[k], L1);
            P0 = fmaf(ak, rw0[k],  P0);
            P1 = fmaf(ak, rw1[k],  P1);
        }
        float redL[2];
        redL[0] = L0 + L1;
        redL[1] = L0*L0 + L1*L1;
        wsumv<2>(redL);
        float sL = redL[0], sL2 = redL[1];

        // ---- LN + MLP fold ----
        float mean = (sL + sumg)*(1.f/192.f);
        float var  = (sL2 + sumg2)*(1.f/192.f) - mean*mean;
        float rstd = rsqrtf(var + 1e-5f);
        float h0 = fmaf(rstd, (P0+Pg0) - mean*gcol_s[lane],    cadd_s[lane]);
        float h1 = fmaf(rstd, (P1+Pg1) - mean*gcol_s[32+lane], cadd_s[32+lane]);
        float gelu0 = 0.5f*h0*(1.f + erff(h0*0.70710678118654752f));
        float gelu1 = 0.5f*h1*(1.f + erff(h1*0.70710678118654752f));
        float pr = wsum(fmaf(gelu0, wm2_s[lane], gelu1*wm2_s[32+lane]));
        if (lane == 0){
            out[b*NS + n] = mn ? (pr + bm2v) : 0.f;
        }
    }
}

// ------------------------- launch -------------------------
extern "C" void kernel_launch(void* const* d_in, const int* in_sizes, int n_in,
                              void* d_out, int out_size){
    const float* xf    = (const float*)d_in[0];
    const float* latent= (const float*)d_in[1];
    const float* pos   = (const float*)d_in[2];
    const float* femb  = (const float*)d_in[3];
    const float* Wnbr  = (const float*)d_in[4];
    const float* bnbr  = (const float*)d_in[5];
    const float* Wql   = (const float*)d_in[6];
    const float* bql   = (const float*)d_in[7];
    const float* Wlat  = (const float*)d_in[8];
    const float* blat  = (const float*)d_in[9];
    const float* Wlf   = (const float*)d_in[10];
    const float* blf   = (const float*)d_in[11];
    const float* Wqg   = (const float*)d_in[12];
    const float* bqg   = (const float*)d_in[13];
    const float* Wk    = (const float*)d_in[14];
    const float* bk    = (const float*)d_in[15];
    const float* Wv    = (const float*)d_in[16];
    const float* bv    = (const float*)d_in[17];
    const float* Wgo   = (const float*)d_in[18];
    const float* bgo   = (const float*)d_in[19];
    const float* lng   = (const float*)d_in[20];
    const float* lnb   = (const float*)d_in[21];
    const float* Wm1   = (const float*)d_in[22];
    const float* bm1   = (const float*)d_in[23];
    const float* Wm2   = (const float*)d_in[24];
    const float* bm2   = (const float*)d_in[25];
    const int* mask    = (const int*)d_in[26];
    const int* knn     = (const int*)d_in[27];
    const int* fid     = (const int*)d_in[28];
    float* out = (float*)d_out;

    cudaFuncSetAttribute(kGEMM, cudaFuncAttributeMaxDynamicSharedMemorySize, 16896*4);

    kPrep<<<116,256>>>(pos, femb, fid, Wnbr, bnbr, Wql, bql, Wqg, bqg, lng, lnb, Wm1, bm1,
                       latent, Wlat, blat, Wlf, blf, Wk, bk, Wv, bv, Wgo, bgo);
    kGEMM<<<dim3(75,7),256,16896*4>>>(lng, Wm1);
    kFH<<<dim3(38,16),128>>>();
    kG<<<595,256>>>(xf, mask, knn, Wnbr, Wm2, bm2, out);
}

// round 8
// speedup vs baseline: 1.1631x; 1.0414x over previous
#include <cuda_runtime.h>
#include <math.h>
#include <math_constants.h>

#define NS 4760
#define NB 16
#define NT 6
#define NBLK 148
#define FULLM 0xffffffffu

// ------------------------- device scratch -------------------------
__device__ float g_q  [NS*128];
__device__ float g_Wpack[128*328 + 64];   // +64 pad for tail-tile staging reads
__device__ float g_bpack[328];
__device__ float g_ql [NS*64];
__device__ float g_sp [NS*64];
__device__ float g_spW[NS*64];
__device__ float g_qg [NS*128];
__device__ float g_a0 [NS];
__device__ float g_a1 [NS];
__device__ float g_kg [NB*NT*128];
__device__ float g_vgo [NB*25*128];
__device__ float g_vgoW[NB*25*64];
__device__ float g_sumv[NB*25];
__device__ float g_gram[NB*25*25];
__device__ float g_pg  [(size_t)NB*NS*68];   // [b][n][68]
__device__ float g_cst [256];
__device__ float g_xq  [NS*32];              // [n][b][2] transposed x
__device__ unsigned g_mb[NS];                // per-n mask bits over b
__device__ unsigned g_tkt[4];                // tickets (reset each run in phase A)
__device__ unsigned g_barcnt[4];             // self-resetting barrier counters

__device__ __forceinline__ float wsum(float v){
    #pragma unroll
    for (int o=16;o;o>>=1) v += __shfl_xor_sync(FULLM, v, o);
    return v;
}
__device__ __forceinline__ float wmax(float v){
    #pragma unroll
    for (int o=16;o;o>>=1) v = fmaxf(v, __shfl_xor_sync(FULLM, v, o));
    return v;
}
template<int N>
__device__ __forceinline__ void wsumv(float* v){
    #pragma unroll
    for (int o=16;o;o>>=1){
        #pragma unroll
        for (int i=0;i<N;i++) v[i] += __shfl_xor_sync(FULLM, v[i], o);
    }
}

// self-resetting device-wide barrier (all CTAs resident by construction)
__device__ __forceinline__ void gbar(int i){
    __syncthreads();
    if (threadIdx.x == 0){
        __threadfence();
        unsigned old = atomicAdd(&g_barcnt[i], 1);
        if (old == NBLK-1){
            atomicExch(&g_barcnt[i], 0);
        } else {
            while (atomicAdd(&g_barcnt[i], 0) != 0) { }
        }
        __threadfence();
    }
    __syncthreads();
}

// ------------------------- the one kernel -------------------------
__global__ void __launch_bounds__(512,1) kAll(
    const float* __restrict__ xf,    const float* __restrict__ latent,
    const float* __restrict__ pos,   const float* __restrict__ femb,
    const float* __restrict__ Wnbr,  const float* __restrict__ bnbr,
    const float* __restrict__ Wql,   const float* __restrict__ bql,
    const float* __restrict__ Wlat,  const float* __restrict__ blat,
    const float* __restrict__ Wlf,   const float* __restrict__ blf,
    const float* __restrict__ Wqg,   const float* __restrict__ bqg,
    const float* __restrict__ Wk,    const float* __restrict__ bk,
    const float* __restrict__ Wv,    const float* __restrict__ bv,
    const float* __restrict__ Wgo,   const float* __restrict__ bgo,
    const float* __restrict__ lng,   const float* __restrict__ lnb,
    const float* __restrict__ Wm1,   const float* __restrict__ bm1,
    const float* __restrict__ Wm2,   const float* __restrict__ bm2,
    const int*   __restrict__ mask,  const int* __restrict__ knn,
    const int*   __restrict__ fid,   float* __restrict__ out)
{
    extern __shared__ float smp[];
    __shared__ int s_t;
    int tid = threadIdx.x;
    int bid = blockIdx.x;
    int lane = tid & 31;

    // ===================== PHASE A =====================
    if (bid < 96){
        // latent path for (b,t)
        float* lat_s = smp;           // 1056
        float* part  = smp + 1056;    // 512
        float* kv_s  = smp + 1568;    // 128
        float* vg_s  = smp + 1696;    // 128
        int t = bid % NT, b = bid / NT;
        for (int e=tid;e<1024;e+=512) lat_s[e] = latent[((size_t)b*NT+t)*1024 + e];
        if (tid < 32) lat_s[1024+tid] = femb[t*32+tid];
        __syncthreads();
        int j = tid & 127, q = tid >> 7;
        {
            float acc = (q==0) ? (blat[j]+blf[j]) : 0.f;
            int i0 = q*256, i1 = i0+256;
            #pragma unroll 4
            for (int i=i0;i<i1;i++) acc = fmaf(lat_s[i], Wlat[i*128+j], acc);
            if (q==3){
                for (int f=0;f<32;f++) acc = fmaf(lat_s[1024+f], Wlf[f*128+j], acc);
            }
            part[q*128+j] = acc;
        }
        __syncthreads();
        if (tid < 128) kv_s[tid] = part[tid] + part[128+tid] + part[256+tid] + part[384+tid];
        __syncthreads();
        {
            const float* W = (q < 2) ? Wk : Wv;
            float acc = 0.f;
            int i0 = (q & 1)*64, i1 = i0+64;
            #pragma unroll 4
            for (int i=i0;i<i1;i++) acc = fmaf(kv_s[i], W[i*128+j], acc);
            part[q*128+j] = acc;
        }
        __syncthreads();
        if (tid < 128) g_kg[(b*NT+t)*128 + tid] = part[tid] + part[128+tid] + bk[tid];
        else if (tid < 256){ int jj = tid-128; vg_s[jj] = part[256+jj] + part[384+jj] + bv[jj]; }
        __syncthreads();
        {
            int h = tid >> 7, j2 = tid & 127;
            float a = 0.f;
            #pragma unroll
            for (int d=0;d<32;d++) a = fmaf(vg_s[h*32+d], Wgo[(h*32+d)*128+j2], a);
            g_vgo[((size_t)b*25 + t*4 + h)*128 + j2] = a;
        }
        if (t==0 && tid<128) g_vgo[((size_t)b*25 + 24)*128 + tid] = bgo[tid];
    } else if (bid == 96){
        // tickets reset + weight pack + consts
        if (tid == 0){ g_tkt[0]=0; g_tkt[1]=0; g_tkt[2]=0; g_tkt[3]=0; }
        float* W1t = smp;   // 4096: lng[i]*Wm1[i][j], i<64
        for (int e=tid;e<4096;e+=512) W1t[e] = lng[e>>6]*Wm1[e];
        __syncthreads();
        for (int e=tid;e<8192;e+=512){
            int k=e>>6, j=e&63;
            g_Wpack[k*328 + j]      = Wql[e];
            g_Wpack[k*328 + 64 + j] = Wnbr[128+e];
        }
        for (int e=tid;e<16384;e+=512){
            int k=e>>7, j=e&127;
            g_Wpack[k*328 + 128 + j] = Wqg[e];
        }
        for (int e=tid;e<8192;e+=512){
            int c=e>>6, j=e&63;
            float a = 0.f;
            #pragma unroll 4
            for (int i=0;i<64;i++) a = fmaf(Wnbr[128 + c*64 + i], W1t[i*64+j], a);
            g_Wpack[c*328 + 256 + j] = a;
        }
        if (tid < 256){
            int k = tid & 127, which = tid >> 7;
            float a = 0.f;
            for (int i=0;i<64;i++) a = fmaf(Wql[k*64+i], Wnbr[which*64 + i], a);
            g_Wpack[k*328 + 320 + which] = a;
        }
        if (tid < 128){
            for (int c=322;c<328;c++) g_Wpack[tid*328+c] = 0.f;
        }
        if (tid < 64){
            g_bpack[tid]      = bql[tid];
            g_bpack[64+tid]   = bnbr[tid];
            float bf = 0.f;
            for (int i=0;i<64;i++) bf = fmaf(bnbr[i], W1t[i*64+tid], bf);
            g_bpack[256+tid] = bf;
        }
        if (tid < 128) g_bpack[128+tid] = bqg[tid];
        if (tid == 0){
            float a0=0.f, a1=0.f;
            for (int i=0;i<64;i++){ a0 = fmaf(bql[i], Wnbr[i], a0); a1 = fmaf(bql[i], Wnbr[64+i], a1); }
            g_bpack[320] = a0; g_bpack[321] = a1;
        }
        if (tid < 64){
            int j = tid;
            float w0W=0.f, w1W=0.f, gcol=0.f, cadd=0.f;
            for (int i=0;i<192;i++){
                float w = Wm1[i*64+j];
                gcol += lng[i]*w;
                cadd += lnb[i]*w;
            }
            for (int i=0;i<64;i++){
                float w = lng[i]*Wm1[i*64+j];
                w0W += Wnbr[i]     * w;
                w1W += Wnbr[64+i]  * w;
            }
            g_cst[j]      = w0W;
            g_cst[64+j]   = w1W;
            g_cst[128+j]  = gcol;
            g_cst[192+j]  = cadd + bm1[j];
        }
    } else if (bid < 116){
        // query matrix build
        int n0 = (bid - 97) * 256;
        for (int e=tid;e<256*128;e+=512){
            int s = e>>7, k = e&127, n = n0 + s;
            if (n >= NS) break;
            g_q[n*128 + k] = (k<96) ? pos[n*96+k] : femb[fid[n]*32 + (k-96)];
        }
    } else {
        // x transpose + mask bits: 32 blocks
        int tb = bid - 116;
        int nlo = tb*149, nhi = nlo+149; if (nhi > NS) nhi = NS;
        for (int n = nlo + tid; n < nhi; n += 512){
            unsigned mb = 0;
            #pragma unroll
            for (int b=0;b<16;b+=2){
                float2 xa = *(const float2*)(xf + ((size_t)b*NS + n)*2);
                float2 xb = *(const float2*)(xf + ((size_t)(b+1)*NS + n)*2);
                float4 o; o.x=xa.x; o.y=xa.y; o.z=xb.x; o.w=xb.y;
                *(float4*)(g_xq + n*32 + b*2) = o;
                if (mask[b*NS+n])     mb |= (1u<<b);
                if (mask[(b+1)*NS+n]) mb |= (1u<<(b+1));
            }
            g_mb[n] = mb;
        }
    }

    gbar(0);

    // ===================== PHASE B: GEMM tiles + folds =====================
    {
        float* AT = smp;            // 128*68 = 8704
        float* Ws = smp + 8704;     // 128*64 = 8192
        for (;;){
            __syncthreads();
            if (tid == 0) s_t = (int)atomicAdd(&g_tkt[0], 1);
            __syncthreads();
            int tt = s_t;
            if (tt >= 450) break;
            int n0 = (tt/6)*64, c0 = (tt%6)*64;
            for (int e=tid;e<8192;e+=512){
                int s = e>>7, k = e&127, n = n0+s;
                AT[k*68 + s] = (n<NS) ? g_q[n*128 + k] : 0.f;
            }
            for (int e=tid;e<8192;e+=512){
                int k = e>>6, cc = e&63;
                Ws[e] = g_Wpack[k*328 + c0 + cc];
            }
            __syncthreads();

            int cg = tid & 15, sg = tid >> 4;   // sg 0..31, 2 sensors each
            const float4* Wb = (const float4*)Ws + cg;
            float acc[2][4];
            #pragma unroll
            for (int s=0;s<2;s++){ acc[s][0]=0.f; acc[s][1]=0.f; acc[s][2]=0.f; acc[s][3]=0.f; }
            #pragma unroll 4
            for (int k=0;k<128;k++){
                float4 w = Wb[k*16];
                float a0 = AT[k*68 + sg*2];
                float a1 = AT[k*68 + sg*2 + 1];
                acc[0][0] = fmaf(a0, w.x, acc[0][0]);
                acc[0][1] = fmaf(a0, w.y, acc[0][1]);
                acc[0][2] = fmaf(a0, w.z, acc[0][2]);
                acc[0][3] = fmaf(a0, w.w, acc[0][3]);
                acc[1][0] = fmaf(a1, w.x, acc[1][0]);
                acc[1][1] = fmaf(a1, w.y, acc[1][1]);
                acc[1][2] = fmaf(a1, w.z, acc[1][2]);
                acc[1][3] = fmaf(a1, w.w, acc[1][3]);
            }
            #pragma unroll
            for (int s=0;s<2;s++){
                int n = n0 + sg*2 + s;
                if (n >= NS) continue;
                #pragma unroll
                for (int u=0;u<4;u++){
                    int c = c0 + cg*4 + u;
                    if (c >= 322) continue;
                    float v = acc[s][u] + g_bpack[c];
                    if (c < 64)        g_ql [n*64 + c]        = v;
                    else if (c < 128)  g_sp [n*64 + (c-64)]   = v;
                    else if (c < 256)  g_qg [n*128 + (c-128)] = v;
                    else if (c < 320)  g_spW[n*64 + (c-256)]  = v;
                    else if (c == 320) g_a0[n] = v;
                    else               g_a1[n] = v;
                }
            }
        }
        // folds
        __syncthreads();
        float* w1bT = smp;   // 64*132 = 8448
        for (int e=tid;e<8192;e+=512){ int c=e>>6, j=e&63; w1bT[j*132+c] = lng[64+c]*Wm1[4096+e]; }
        __syncthreads();
        int c4 = lane*4;
        for (;;){
            int base;
            if (lane == 0) base = (int)atomicAdd(&g_tkt[1], 8);
            base = __shfl_sync(FULLM, base, 0);
            if (base >= 36000) break;
            #pragma unroll
            for (int k8=0;k8<8;k8++){
                int task = base + k8;
                if (task >= 36000) break;
                int b = task/2250, tt2 = task - b*2250;
                if (tt2 < 1600){
                    int i = tt2 >> 6, j = tt2 & 63;
                    float4 a = *(const float4*)(g_vgo + ((size_t)b*25+i)*128 + c4);
                    float4 w = *(const float4*)(w1bT + j*132 + c4);
                    float v = a.x*w.x + a.y*w.y + a.z*w.z + a.w*w.w;
                    v = wsum(v);
                    if (lane==0) g_vgoW[(b*25+i)*64 + j] = v;
                } else if (tt2 < 2225){
                    int p = tt2 - 1600, i1 = p/25, i2 = p - i1*25;
                    float4 a = *(const float4*)(g_vgo + ((size_t)b*25+i1)*128 + c4);
                    float4 c = *(const float4*)(g_vgo + ((size_t)b*25+i2)*128 + c4);
                    float v = a.x*c.x + a.y*c.y + a.z*c.z + a.w*c.w;
                    v = wsum(v);
                    if (lane==0) g_gram[b*625 + p] = v;
                } else {
                    int i = tt2 - 2225;
                    float4 a = *(const float4*)(g_vgo + ((size_t)b*25+i)*128 + c4);
                    float v = a.x + a.y + a.z + a.w;
                    v = wsum(v);
                    if (lane==0) g_sumv[b*25 + i] = v;
                }
            }
        }
    }

    gbar(1);

    // ===================== PHASE C: global softmax + Pg =====================
    {
        float* qs     = smp;              // 128*133 = 17024
        float* Ks     = smp + 17024;      // 768
        float* vgoW_s = smp + 17792;      // 1600
        float* gram_s = smp + 19392;      // 700
        float* sumv_s = smp + 20092;      // 32
        float* gax    = smp + 20124;      // 128*27 = 3456
        const float scale = 0.17677669529663687f;
        for (;;){
            __syncthreads();
            if (tid == 0) s_t = (int)atomicAdd(&g_tkt[2], 1);
            __syncthreads();
            int tt = s_t;
            if (tt >= 608) break;
            int b = tt & 15, n0 = (tt >> 4)*128;

            for (int e=tid;e<768;e+=512){
                int r=e>>5, k=e&31, h=r/6, t2=r%6;
                Ks[e] = g_kg[(b*NT+t2)*128 + h*32 + k];
            }
            for (int e=tid;e<1600;e+=512) vgoW_s[e] = g_vgoW[b*1600 + e];
            for (int e=tid;e<625;e+=512){ int i=e/25, jj=e-i*25; gram_s[i*28+jj] = g_gram[b*625 + e]; }
            if (tid < 25) sumv_s[tid] = g_sumv[b*25 + tid];
            for (int e=tid;e<16384;e+=512){
                int s=e>>7, k=e&127;
                int nr = (n0+s < NS) ? (n0+s) : (NS-1);
                qs[s*133+k] = g_qg[nr*128 + k];
            }
            __syncthreads();

            int s = tid & 127, q = tid >> 7;   // q = head h
            {
                float qv[32];
                #pragma unroll
                for (int k=0;k<32;k++) qv[k] = qs[s*133 + q*32 + k];
                float lg[6];
                #pragma unroll
                for (int t2=0;t2<6;t2++){
                    const float* kr = Ks + (q*6+t2)*32;
                    float a = 0.f;
                    #pragma unroll
                    for (int k=0;k<32;k++) a = fmaf(qv[k], kr[k], a);
                    lg[t2] = a;
                }
                float m = lg[0];
                #pragma unroll
                for (int t2=1;t2<6;t2++) m = fmaxf(m, lg[t2]);
                float den = 0.f, ex[6];
                #pragma unroll
                for (int t2=0;t2<6;t2++){ ex[t2] = __expf((lg[t2]-m)*scale); den += ex[t2]; }
                float inv = 1.f/den;
                #pragma unroll
                for (int t2=0;t2<6;t2++) gax[s*27 + t2*4 + q] = ex[t2]*inv;
            }
            __syncthreads();

            float ga[25];
            #pragma unroll
            for (int i=0;i<24;i++) ga[i] = gax[s*27 + i];
            ga[24] = 1.f;

            float4 pg4[4];
            {
                const float4* w24 = (const float4*)(vgoW_s + 24*64 + q*16);
                #pragma unroll
                for (int jj=0;jj<4;jj++) pg4[jj] = w24[jj];
            }
            #pragma unroll
            for (int i=0;i<24;i++){
                float g = ga[i];
                const float4* wr = (const float4*)(vgoW_s + i*64 + q*16);
                #pragma unroll
                for (int jj=0;jj<4;jj++){
                    float4 w = wr[jj];
                    pg4[jj].x = fmaf(g, w.x, pg4[jj].x);
                    pg4[jj].y = fmaf(g, w.y, pg4[jj].y);
                    pg4[jj].z = fmaf(g, w.z, pg4[jj].z);
                    pg4[jj].w = fmaf(g, w.w, pg4[jj].w);
                }
            }
            float sumg = 0.f, sumg2 = 0.f;
            if (q == 0){
                sumg = sumv_s[24];
                #pragma unroll
                for (int i=0;i<24;i++) sumg = fmaf(ga[i], sumv_s[i], sumg);
            }
            if (q == 1){
                #pragma unroll
                for (int i=0;i<25;i++){
                    float ti = gram_s[i*28 + 24];
                    #pragma unroll
                    for (int j4=0;j4<6;j4++){
                        float4 gv = *(const float4*)(gram_s + i*28 + j4*4);
                        ti = fmaf(gv.x, ga[j4*4+0], ti);
                        ti = fmaf(gv.y, ga[j4*4+1], ti);
                        ti = fmaf(gv.z, ga[j4*4+2], ti);
                        ti = fmaf(gv.w, ga[j4*4+3], ti);
                    }
                    sumg2 = fmaf(ga[i], ti, sumg2);
                }
            }
            if (n0 + s < NS){
                float* dst = g_pg + ((size_t)b*NS + (n0+s))*68;
                float4* d4 = (float4*)(dst + q*16);
                #pragma unroll
                for (int jj=0;jj<4;jj++) d4[jj] = pg4[jj];
                if (q == 0) dst[64] = sumg;
                if (q == 1) dst[65] = sumg2;
            }
        }
    }

    gbar(2);

    // ===================== PHASE D: fused main =====================
    {
        float* cst = smp;   // 448
        if (tid < 128) cst[tid] = Wnbr[tid];
        if (tid >= 128 && tid < 384) cst[tid] = g_cst[tid-128];
        if (tid >= 384 && tid < 448) cst[tid] = Wm2[tid-384];
        __syncthreads();
        const float* w0_s  = cst;
        const float* w1_s  = cst + 64;
        const float* w0W_s = cst + 128;
        const float* w1W_s = cst + 192;
        const float* gcol_s= cst + 256;
        const float* cadd_s= cst + 320;
        const float* wm2_s = cst + 384;
        float bm2v = bm2[0];

        for (;;){
            int n;
            if (lane == 0) n = (int)atomicAdd(&g_tkt[3], 1);
            n = __shfl_sync(FULLM, n, 0);
            if (n >= NS) break;

            int kj = 0; unsigned mkb = 0;
            if (lane < 16){ kj = knn[n*16 + lane]; mkb = g_mb[kj]; }
            unsigned mbn = g_mb[n];
            float a0 = g_a0[n], a1 = g_a1[n];
            float ql0 = g_ql[n*64 + lane], ql1 = g_ql[n*64 + 32 + lane];
            float rsp0[16], rsp1[16], rw0[16], rw1[16];
            #pragma unroll
            for (int k=0;k<16;k++){
                int j = __shfl_sync(FULLM, kj, k);
                rsp0[k] = g_sp[j*64 + lane];
                rsp1[k] = g_sp[j*64 + 32 + lane];
                rw0[k]  = g_spW[j*64 + lane];
                rw1[k]  = g_spW[j*64 + 32 + lane];
            }
            float Sreg = 0.f;
            #pragma unroll
            for (int k0=0;k0<16;k0+=4){
                float p[4];
                #pragma unroll
                for (int u=0;u<4;u++) p[u] = fmaf(rsp0[k0+u], ql0, rsp1[k0+u]*ql1);
                wsumv<4>(p);
                if (lane == k0)   Sreg = p[0];
                if (lane == k0+1) Sreg = p[1];
                if (lane == k0+2) Sreg = p[2];
                if (lane == k0+3) Sreg = p[3];
            }

            #pragma unroll
            for (int hb=0;hb<2;hb++){
                float4 xq4[4];
                if (lane < 16){
                    const float4* px = (const float4*)(g_xq + kj*32 + hb*16);
                    #pragma unroll
                    for (int u=0;u<4;u++) xq4[u] = px[u];
                }
                #pragma unroll
                for (int bi=0;bi<8;bi++){
                    int b = hb*8 + bi;
                    const float* pg = g_pg + ((size_t)b*NS + n)*68;
                    float Pg0  = pg[lane];
                    float Pg1  = pg[32+lane];
                    float sumg = pg[64];
                    float sumg2= pg[65];

                    float4 xv4 = xq4[bi>>1];
                    float x0 = (bi & 1) ? xv4.z : xv4.x;
                    float x1 = (bi & 1) ? xv4.w : xv4.y;
                    float logit = -CUDART_INF_F;
                    if (lane < 16){
                        bool masked = (mkb >> b) & 1u;
                        logit = masked ? -10000.f : (Sreg + x0*a0 + x1*a1)*0.125f;
                    } else { x0 = 0.f; x1 = 0.f; }

                    float mx = wmax(logit);
                    float e = (lane < 16) ? __expf(logit - mx) : 0.f;
                    float red3[3];
                    red3[0] = e; red3[1] = e*x0; red3[2] = e*x1;
                    wsumv<3>(red3);
                    float inv = 1.f/red3[0];
                    float attn = e*inv;
                    float alpha = red3[1]*inv, beta = red3[2]*inv;

                    float L0 = alpha*w0_s[lane]      + beta*w1_s[lane];
                    float L1 = alpha*w0_s[32+lane]   + beta*w1_s[32+lane];
                    float P0 = alpha*w0W_s[lane]     + beta*w1W_s[lane];
                    float P1 = alpha*w0W_s[32+lane]  + beta*w1W_s[32+lane];
                    #pragma unroll
                    for (int k=0;k<16;k++){
                        float ak = __shfl_sync(FULLM, attn, k);
                        L0 = fmaf(ak, rsp0[k], L0);
                        L1 = fmaf(ak, rsp1[k], L1);
                        P0 = fmaf(ak, rw0[k],  P0);
                        P1 = fmaf(ak, rw1[k],  P1);
                    }
                    float redL[2];
                    redL[0] = L0 + L1;
                    redL[1] = L0*L0 + L1*L1;
                    wsumv<2>(redL);

                    float mean = (redL[0] + sumg)*(1.f/192.f);
                    float var  = (redL[1] + sumg2)*(1.f/192.f) - mean*mean;
                    float rstd = rsqrtf(var + 1e-5f);
                    float h0 = fmaf(rstd, (P0+Pg0) - mean*gcol_s[lane],    cadd_s[lane]);
                    float h1 = fmaf(rstd, (P1+Pg1) - mean*gcol_s[32+lane], cadd_s[32+lane]);
                    float gelu0 = 0.5f*h0*(1.f + erff(h0*0.70710678118654752f));
                    float gelu1 = 0.5f*h1*(1.f + erff(h1*0.70710678118654752f));
                    float pr = wsum(fmaf(gelu0, wm2_s[lane], gelu1*wm2_s[32+lane]));
                    if (lane == 0){
                        int mn = (mbn >> b) & 1u;
                        out[b*NS + n] = mn ? (pr + bm2v) : 0.f;
                    }
                }
            }
        }
    }
}

// ------------------------- launch -------------------------
extern "C" void kernel_launch(void* const* d_in, const int* in_sizes, int n_in,
                              void* d_out, int out_size){
    const float* xf    = (const float*)d_in[0];
    const float* latent= (const float*)d_in[1];
    const float* pos   = (const float*)d_in[2];
    const float* femb  = (const float*)d_in[3];
    const float* Wnbr  = (const float*)d_in[4];
    const float* bnbr  = (const float*)d_in[5];
    const float* Wql   = (const float*)d_in[6];
    const float* bql   = (const float*)d_in[7];
    const float* Wlat  = (const float*)d_in[8];
    const float* blat  = (const float*)d_in[9];
    const float* Wlf   = (const float*)d_in[10];
    const float* blf   = (const float*)d_in[11];
    const float* Wqg   = (const float*)d_in[12];
    const float* bqg   = (const float*)d_in[13];
    const float* Wk    = (const float*)d_in[14];
    const float* bk    = (const float*)d_in[15];
    const float* Wv    = (const float*)d_in[16];
    const float* bv    = (const float*)d_in[17];
    const float* Wgo   = (const float*)d_in[18];
    const float* bgo   = (const float*)d_in[19];
    const float* lng   = (const float*)d_in[20];
    const float* lnb   = (const float*)d_in[21];
    const float* Wm1   = (const float*)d_in[22];
    const float* bm1   = (const float*)d_in[23];
    const float* Wm2   = (const float*)d_in[24];
    const float* bm2   = (const float*)d_in[25];
    const int* mask    = (const int*)d_in[26];
    const int* knn     = (const int*)d_in[27];
    const int* fid     = (const int*)d_in[28];
    float* out = (float*)d_out;

    static int smem_sz = 23580*4;
    cudaFuncSetAttribute(kAll, cudaFuncAttributeMaxDynamicSharedMemorySize, smem_sz);

    kAll<<<NBLK, 512, smem_sz>>>(
        xf, latent, pos, femb, Wnbr, bnbr, Wql, bql, Wlat, blat, Wlf, blf,
        Wqg, bqg, Wk, bk, Wv, bv, Wgo, bgo, lng, lnb, Wm1, bm1, Wm2, bm2,
        mask, knn, fid, out);
}

// round 9
// speedup vs baseline: 1.2189x; 1.0480x over previous
#include <cuda_runtime.h>
#include <math.h>
#include <math_constants.h>

#define NS 4760
#define NB 16
#define NT 6
#define NBLK 148
#define FULLM 0xffffffffu

// ------------------------- device scratch -------------------------
__device__ float g_q  [NS*128];
__device__ float g_Wpack[128*328 + 64];
__device__ float g_bpack[328];
__device__ float g_ql [NS*64];
__device__ float g_sp [NS*64];
__device__ float g_spW[NS*64];
__device__ float g_qg [NS*128];
__device__ float g_a0 [NS];
__device__ float g_a1 [NS];
__device__ float g_kg [NB*NT*128];
__device__ float g_vgo [NB*25*128];
__device__ float g_vgoW[NB*25*64];
__device__ float g_sumv[NB*25];
__device__ float g_gram[NB*25*25];
__device__ float g_pg  [(size_t)NB*NS*68];   // [b][n][68]
__device__ float g_cst [256];
__device__ float g_xq  [NS*32];              // [n][b][2]
__device__ unsigned g_mb[NS];
__device__ unsigned g_tkt[4];
__device__ unsigned g_barcnt[4];

__device__ __forceinline__ float wsum(float v){
    #pragma unroll
    for (int o=16;o;o>>=1) v += __shfl_xor_sync(FULLM, v, o);
    return v;
}
template<int N>
__device__ __forceinline__ void wsumv(float* v){
    #pragma unroll
    for (int o=16;o;o>>=1){
        #pragma unroll
        for (int i=0;i<N;i++) v[i] += __shfl_xor_sync(FULLM, v[i], o);
    }
}

__device__ __forceinline__ void gbar(int i){
    __syncthreads();
    if (threadIdx.x == 0){
        __threadfence();
        unsigned old = atomicAdd(&g_barcnt[i], 1);
        if (old == NBLK-1){
            atomicExch(&g_barcnt[i], 0);
        } else {
            while (atomicAdd(&g_barcnt[i], 0) != 0) { }
        }
        __threadfence();
    }
    __syncthreads();
}

// ------------------------- the one kernel -------------------------
__global__ void __launch_bounds__(512,1) kAll(
    const float* __restrict__ xf,    const float* __restrict__ latent,
    const float* __restrict__ pos,   const float* __restrict__ femb,
    const float* __restrict__ Wnbr,  const float* __restrict__ bnbr,
    const float* __restrict__ Wql,   const float* __restrict__ bql,
    const float* __restrict__ Wlat,  const float* __restrict__ blat,
    const float* __restrict__ Wlf,   const float* __restrict__ blf,
    const float* __restrict__ Wqg,   const float* __restrict__ bqg,
    const float* __restrict__ Wk,    const float* __restrict__ bk,
    const float* __restrict__ Wv,    const float* __restrict__ bv,
    const float* __restrict__ Wgo,   const float* __restrict__ bgo,
    const float* __restrict__ lng,   const float* __restrict__ lnb,
    const float* __restrict__ Wm1,   const float* __restrict__ bm1,
    const float* __restrict__ Wm2,   const float* __restrict__ bm2,
    const int*   __restrict__ mask,  const int* __restrict__ knn,
    const int*   __restrict__ fid,   float* __restrict__ out)
{
    extern __shared__ float smp[];
    __shared__ int s_t;
    int tid = threadIdx.x;
    int bid = blockIdx.x;
    int lane = tid & 31;

    // ===================== PHASE A =====================
    if (bid < 96){
        float* lat_s = smp;           // 1056
        float* part  = smp + 1056;    // 512
        float* kv_s  = smp + 1568;    // 128
        float* vg_s  = smp + 1696;    // 128
        int t = bid % NT, b = bid / NT;
        for (int e=tid;e<1024;e+=512) lat_s[e] = latent[((size_t)b*NT+t)*1024 + e];
        if (tid < 32) lat_s[1024+tid] = femb[t*32+tid];
        __syncthreads();
        int j = tid & 127, q = tid >> 7;
        {
            float acc = (q==0) ? (blat[j]+blf[j]) : 0.f;
            int i0 = q*256, i1 = i0+256;
            #pragma unroll 4
            for (int i=i0;i<i1;i++) acc = fmaf(lat_s[i], Wlat[i*128+j], acc);
            if (q==3){
                for (int f=0;f<32;f++) acc = fmaf(lat_s[1024+f], Wlf[f*128+j], acc);
            }
            part[q*128+j] = acc;
        }
        __syncthreads();
        if (tid < 128) kv_s[tid] = part[tid] + part[128+tid] + part[256+tid] + part[384+tid];
        __syncthreads();
        {
            const float* W = (q < 2) ? Wk : Wv;
            float acc = 0.f;
            int i0 = (q & 1)*64, i1 = i0+64;
            #pragma unroll 4
            for (int i=i0;i<i1;i++) acc = fmaf(kv_s[i], W[i*128+j], acc);
            part[q*128+j] = acc;
        }
        __syncthreads();
        if (tid < 128) g_kg[(b*NT+t)*128 + tid] = part[tid] + part[128+tid] + bk[tid];
        else if (tid < 256){ int jj = tid-128; vg_s[jj] = part[256+jj] + part[384+jj] + bv[jj]; }
        __syncthreads();
        {
            int h = tid >> 7, j2 = tid & 127;
            float a = 0.f;
            #pragma unroll
            for (int d=0;d<32;d++) a = fmaf(vg_s[h*32+d], Wgo[(h*32+d)*128+j2], a);
            g_vgo[((size_t)b*25 + t*4 + h)*128 + j2] = a;
        }
        if (t==0 && tid<128) g_vgo[((size_t)b*25 + 24)*128 + tid] = bgo[tid];
    } else if (bid == 96){
        if (tid == 0){ g_tkt[0]=0; g_tkt[1]=0; g_tkt[2]=0; g_tkt[3]=0; }
        float* W1t = smp;
        for (int e=tid;e<4096;e+=512) W1t[e] = lng[e>>6]*Wm1[e];
        __syncthreads();
        for (int e=tid;e<8192;e+=512){
            int k=e>>6, j=e&63;
            g_Wpack[k*328 + j]      = Wql[e];
            g_Wpack[k*328 + 64 + j] = Wnbr[128+e];
        }
        for (int e=tid;e<16384;e+=512){
            int k=e>>7, j=e&127;
            g_Wpack[k*328 + 128 + j] = Wqg[e];
        }
        for (int e=tid;e<8192;e+=512){
            int c=e>>6, j=e&63;
            float a = 0.f;
            #pragma unroll 4
            for (int i=0;i<64;i++) a = fmaf(Wnbr[128 + c*64 + i], W1t[i*64+j], a);
            g_Wpack[c*328 + 256 + j] = a;
        }
        if (tid < 256){
            int k = tid & 127, which = tid >> 7;
            float a = 0.f;
            for (int i=0;i<64;i++) a = fmaf(Wql[k*64+i], Wnbr[which*64 + i], a);
            g_Wpack[k*328 + 320 + which] = a;
        }
        if (tid < 128){
            for (int c=322;c<328;c++) g_Wpack[tid*328+c] = 0.f;
        }
        if (tid < 64){
            g_bpack[tid]      = bql[tid];
            g_bpack[64+tid]   = bnbr[tid];
            float bf = 0.f;
            for (int i=0;i<64;i++) bf = fmaf(bnbr[i], W1t[i*64+tid], bf);
            g_bpack[256+tid] = bf;
        }
        if (tid < 128) g_bpack[128+tid] = bqg[tid];
        if (tid == 0){
            float a0=0.f, a1=0.f;
            for (int i=0;i<64;i++){ a0 = fmaf(bql[i], Wnbr[i], a0); a1 = fmaf(bql[i], Wnbr[64+i], a1); }
            g_bpack[320] = a0; g_bpack[321] = a1;
        }
        if (tid < 64){
            int j = tid;
            float w0W=0.f, w1W=0.f, gcol=0.f, cadd=0.f;
            for (int i=0;i<192;i++){
                float w = Wm1[i*64+j];
                gcol += lng[i]*w;
                cadd += lnb[i]*w;
            }
            for (int i=0;i<64;i++){
                float w = lng[i]*Wm1[i*64+j];
                w0W += Wnbr[i]     * w;
                w1W += Wnbr[64+i]  * w;
            }
            g_cst[j]      = w0W;
            g_cst[64+j]   = w1W;
            g_cst[128+j]  = gcol;
            g_cst[192+j]  = cadd + bm1[j];
        }
    } else if (bid < 116){
        int n0 = (bid - 97) * 256;
        for (int e=tid;e<256*128;e+=512){
            int s = e>>7, k = e&127, n = n0 + s;
            if (n >= NS) break;
            g_q[n*128 + k] = (k<96) ? pos[n*96+k] : femb[fid[n]*32 + (k-96)];
        }
    } else {
        int tb = bid - 116;
        int nlo = tb*149, nhi = nlo+149; if (nhi > NS) nhi = NS;
        for (int n = nlo + tid; n < nhi; n += 512){
            unsigned mb = 0;
            #pragma unroll
            for (int b=0;b<16;b+=2){
                float2 xa = *(const float2*)(xf + ((size_t)b*NS + n)*2);
                float2 xb = *(const float2*)(xf + ((size_t)(b+1)*NS + n)*2);
                float4 o; o.x=xa.x; o.y=xa.y; o.z=xb.x; o.w=xb.y;
                *(float4*)(g_xq + n*32 + b*2) = o;
                if (mask[b*NS+n])     mb |= (1u<<b);
                if (mask[(b+1)*NS+n]) mb |= (1u<<(b+1));
            }
            g_mb[n] = mb;
        }
    }

    gbar(0);

    // ===================== PHASE B: GEMM tiles + folds =====================
    {
        float* AT = smp;            // 8704
        float* Ws = smp + 8704;     // 8192
        for (;;){
            __syncthreads();
            if (tid == 0) s_t = (int)atomicAdd(&g_tkt[0], 1);
            __syncthreads();
            int tt = s_t;
            if (tt >= 450) break;
            int n0 = (tt/6)*64, c0 = (tt%6)*64;
            for (int e=tid;e<8192;e+=512){
                int s = e>>7, k = e&127, n = n0+s;
                AT[k*68 + s] = (n<NS) ? g_q[n*128 + k] : 0.f;
            }
            for (int e=tid;e<8192;e+=512){
                int k = e>>6, cc = e&63;
                Ws[e] = g_Wpack[k*328 + c0 + cc];
            }
            __syncthreads();

            int cg = tid & 15, sg = tid >> 4;
            const float4* Wb = (const float4*)Ws + cg;
            float acc[2][4];
            #pragma unroll
            for (int s=0;s<2;s++){ acc[s][0]=0.f; acc[s][1]=0.f; acc[s][2]=0.f; acc[s][3]=0.f; }
            #pragma unroll 4
            for (int k=0;k<128;k++){
                float4 w = Wb[k*16];
                float a0 = AT[k*68 + sg*2];
                float a1 = AT[k*68 + sg*2 + 1];
                acc[0][0] = fmaf(a0, w.x, acc[0][0]);
                acc[0][1] = fmaf(a0, w.y, acc[0][1]);
                acc[0][2] = fmaf(a0, w.z, acc[0][2]);
                acc[0][3] = fmaf(a0, w.w, acc[0][3]);
                acc[1][0] = fmaf(a1, w.x, acc[1][0]);
                acc[1][1] = fmaf(a1, w.y, acc[1][1]);
                acc[1][2] = fmaf(a1, w.z, acc[1][2]);
                acc[1][3] = fmaf(a1, w.w, acc[1][3]);
            }
            #pragma unroll
            for (int s=0;s<2;s++){
                int n = n0 + sg*2 + s;
                if (n >= NS) continue;
                #pragma unroll
                for (int u=0;u<4;u++){
                    int c = c0 + cg*4 + u;
                    if (c >= 322) continue;
                    float v = acc[s][u] + g_bpack[c];
                    if (c < 64)        g_ql [n*64 + c]        = v;
                    else if (c < 128)  g_sp [n*64 + (c-64)]   = v;
                    else if (c < 256)  g_qg [n*128 + (c-128)] = v;
                    else if (c < 320)  g_spW[n*64 + (c-256)]  = v;
                    else if (c == 320) g_a0[n] = v;
                    else               g_a1[n] = v;
                }
            }
        }
        __syncthreads();
        float* w1bT = smp;   // 8448
        for (int e=tid;e<8192;e+=512){ int c=e>>6, j=e&63; w1bT[j*132+c] = lng[64+c]*Wm1[4096+e]; }
        __syncthreads();
        int c4 = lane*4;
        for (;;){
            int base;
            if (lane == 0) base = (int)atomicAdd(&g_tkt[1], 8);
            base = __shfl_sync(FULLM, base, 0);
            if (base >= 36000) break;
            #pragma unroll
            for (int k8=0;k8<8;k8++){
                int task = base + k8;
                if (task >= 36000) break;
                int b = task/2250, tt2 = task - b*2250;
                if (tt2 < 1600){
                    int i = tt2 >> 6, j = tt2 & 63;
                    float4 a = *(const float4*)(g_vgo + ((size_t)b*25+i)*128 + c4);
                    float4 w = *(const float4*)(w1bT + j*132 + c4);
                    float v = a.x*w.x + a.y*w.y + a.z*w.z + a.w*w.w;
                    v = wsum(v);
                    if (lane==0) g_vgoW[(b*25+i)*64 + j] = v;
                } else if (tt2 < 2225){
                    int p = tt2 - 1600, i1 = p/25, i2 = p - i1*25;
                    float4 a = *(const float4*)(g_vgo + ((size_t)b*25+i1)*128 + c4);
                    float4 c = *(const float4*)(g_vgo + ((size_t)b*25+i2)*128 + c4);
                    float v = a.x*c.x + a.y*c.y + a.z*c.z + a.w*c.w;
                    v = wsum(v);
                    if (lane==0) g_gram[b*625 + p] = v;
                } else {
                    int i = tt2 - 2225;
                    float4 a = *(const float4*)(g_vgo + ((size_t)b*25+i)*128 + c4);
                    float v = a.x + a.y + a.z + a.w;
                    v = wsum(v);
                    if (lane==0) g_sumv[b*25 + i] = v;
                }
            }
        }
    }

    gbar(1);

    // ===================== PHASE C: global softmax + Pg =====================
    {
        float* qs     = smp;              // 17024
        float* Ks     = smp + 17024;      // 768
        float* vgoW_s = smp + 17792;      // 1600
        float* gram_s = smp + 19392;      // 700
        float* sumv_s = smp + 20092;      // 32
        float* gax    = smp + 20124;      // 3456
        const float scale = 0.17677669529663687f;
        for (;;){
            __syncthreads();
            if (tid == 0) s_t = (int)atomicAdd(&g_tkt[2], 1);
            __syncthreads();
            int tt = s_t;
            if (tt >= 608) break;
            int b = tt & 15, n0 = (tt >> 4)*128;

            for (int e=tid;e<768;e+=512){
                int r=e>>5, k=e&31, h=r/6, t2=r%6;
                Ks[e] = g_kg[(b*NT+t2)*128 + h*32 + k];
            }
            for (int e=tid;e<1600;e+=512) vgoW_s[e] = g_vgoW[b*1600 + e];
            for (int e=tid;e<625;e+=512){ int i=e/25, jj=e-i*25; gram_s[i*28+jj] = g_gram[b*625 + e]; }
            if (tid < 25) sumv_s[tid] = g_sumv[b*25 + tid];
            for (int e=tid;e<16384;e+=512){
                int s=e>>7, k=e&127;
                int nr = (n0+s < NS) ? (n0+s) : (NS-1);
                qs[s*133+k] = g_qg[nr*128 + k];
            }
            __syncthreads();

            int s = tid & 127, q = tid >> 7;
            {
                float qv[32];
                #pragma unroll
                for (int k=0;k<32;k++) qv[k] = qs[s*133 + q*32 + k];
                float lg[6];
                #pragma unroll
                for (int t2=0;t2<6;t2++){
                    const float* kr = Ks + (q*6+t2)*32;
                    float a = 0.f;
                    #pragma unroll
                    for (int k=0;k<32;k++) a = fmaf(qv[k], kr[k], a);
                    lg[t2] = a;
                }
                float m = lg[0];
                #pragma unroll
                for (int t2=1;t2<6;t2++) m = fmaxf(m, lg[t2]);
                float den = 0.f, ex[6];
                #pragma unroll
                for (int t2=0;t2<6;t2++){ ex[t2] = __expf((lg[t2]-m)*scale); den += ex[t2]; }
                float inv = 1.f/den;
                #pragma unroll
                for (int t2=0;t2<6;t2++) gax[s*27 + t2*4 + q] = ex[t2]*inv;
            }
            __syncthreads();

            float ga[25];
            #pragma unroll
            for (int i=0;i<24;i++) ga[i] = gax[s*27 + i];
            ga[24] = 1.f;

            float4 pg4[4];
            {
                const float4* w24 = (const float4*)(vgoW_s + 24*64 + q*16);
                #pragma unroll
                for (int jj=0;jj<4;jj++) pg4[jj] = w24[jj];
            }
            #pragma unroll
            for (int i=0;i<24;i++){
                float g = ga[i];
                const float4* wr = (const float4*)(vgoW_s + i*64 + q*16);
                #pragma unroll
                for (int jj=0;jj<4;jj++){
                    float4 w = wr[jj];
                    pg4[jj].x = fmaf(g, w.x, pg4[jj].x);
                    pg4[jj].y = fmaf(g, w.y, pg4[jj].y);
                    pg4[jj].z = fmaf(g, w.z, pg4[jj].z);
                    pg4[jj].w = fmaf(g, w.w, pg4[jj].w);
                }
            }
            float sumg = 0.f, sumg2 = 0.f;
            if (q == 0){
                sumg = sumv_s[24];
                #pragma unroll
                for (int i=0;i<24;i++) sumg = fmaf(ga[i], sumv_s[i], sumg);
            }
            if (q == 1){
                #pragma unroll
                for (int i=0;i<25;i++){
                    float ti = gram_s[i*28 + 24];
                    #pragma unroll
                    for (int j4=0;j4<6;j4++){
                        float4 gv = *(const float4*)(gram_s + i*28 + j4*4);
                        ti = fmaf(gv.x, ga[j4*4+0], ti);
                        ti = fmaf(gv.y, ga[j4*4+1], ti);
                        ti = fmaf(gv.z, ga[j4*4+2], ti);
                        ti = fmaf(gv.w, ga[j4*4+3], ti);
                    }
                    sumg2 = fmaf(ga[i], ti, sumg2);
                }
            }
            if (n0 + s < NS){
                float* dst = g_pg + ((size_t)b*NS + (n0+s))*68;
                float4* d4 = (float4*)(dst + q*16);
                #pragma unroll
                for (int jj=0;jj<4;jj++) d4[jj] = pg4[jj];
                if (q == 0) dst[64] = sumg;
                if (q == 1) dst[65] = sumg2;
            }
        }
    }

    gbar(2);

    // ===================== PHASE D: fused main (2-b interleaved) =====================
    {
        float* cst = smp;                 // 512
        float* rwT = smp + 512;           // 16 warps x 1024
        if (tid < 128) cst[tid] = Wnbr[tid];
        if (tid >= 128 && tid < 384) cst[tid] = g_cst[tid-128];
        if (tid >= 384 && tid < 448) cst[tid] = Wm2[tid-384];
        __syncthreads();
        const float* w0_s  = cst;
        const float* w1_s  = cst + 64;
        const float* w0W_s = cst + 128;
        const float* w1W_s = cst + 192;
        const float* gcol_s= cst + 256;
        const float* cadd_s= cst + 320;
        const float* wm2_s = cst + 384;
        float bm2v = bm2[0];
        float* myT = rwT + (tid>>5)*1024;

        for (;;){
            int n;
            if (lane == 0) n = (int)atomicAdd(&g_tkt[3], 1);
            n = __shfl_sync(FULLM, n, 0);
            if (n >= NS) break;

            int kj = 0; unsigned mkb = 0;
            if (lane < 16){ kj = knn[n*16 + lane]; mkb = g_mb[kj]; }
            unsigned mbn = g_mb[n];
            float a0 = g_a0[n], a1 = g_a1[n];
            float ql0 = g_ql[n*64 + lane], ql1 = g_ql[n*64 + 32 + lane];
            float rsp0[16], rsp1[16];
            #pragma unroll
            for (int k=0;k<16;k++){
                int j = __shfl_sync(FULLM, kj, k);
                rsp0[k] = g_sp[j*64 + lane];
                rsp1[k] = g_sp[j*64 + 32 + lane];
                myT[k*64 + lane]      = g_spW[j*64 + lane];
                myT[k*64 + 32 + lane] = g_spW[j*64 + 32 + lane];
            }
            float Sreg = 0.f;
            #pragma unroll
            for (int k0=0;k0<16;k0+=4){
                float p[4];
                #pragma unroll
                for (int u=0;u<4;u++) p[u] = fmaf(rsp0[k0+u], ql0, rsp1[k0+u]*ql1);
                wsumv<4>(p);
                if (lane == k0)   Sreg = p[0];
                if (lane == k0+1) Sreg = p[1];
                if (lane == k0+2) Sreg = p[2];
                if (lane == k0+3) Sreg = p[3];
            }

            #pragma unroll
            for (int hb=0;hb<2;hb++){
                float4 xq4[4];
                #pragma unroll
                for (int u=0;u<4;u++){ xq4[u].x=0.f; xq4[u].y=0.f; xq4[u].z=0.f; xq4[u].w=0.f; }
                if (lane < 16){
                    const float4* px = (const float4*)(g_xq + kj*32 + hb*16);
                    #pragma unroll
                    for (int u=0;u<4;u++) xq4[u] = px[u];
                }
                #pragma unroll
                for (int bp=0;bp<4;bp++){
                    int b0 = hb*8 + bp*2, b1 = b0 + 1;
                    const float* pgA = g_pg + ((size_t)b0*NS + n)*68;
                    const float* pgB = g_pg + ((size_t)b1*NS + n)*68;
                    float PgA0 = pgA[lane], PgA1 = pgA[32+lane];
                    float sgA  = pgA[64],   sg2A = pgA[65];
                    float PgB0 = pgB[lane], PgB1 = pgB[32+lane];
                    float sgB  = pgB[64],   sg2B = pgB[65];

                    float4 xv = xq4[bp];
                    float x00 = xv.x, x01 = xv.y, x10 = xv.z, x11 = xv.w;
                    float e0 = 0.f, e1 = 0.f;
                    if (lane < 16){
                        float l0 = (Sreg + x00*a0 + x01*a1)*0.125f;
                        float l1 = (Sreg + x10*a0 + x11*a1)*0.125f;
                        e0 = ((mkb >> b0) & 1u) ? 1e-20f : __expf(l0);
                        e1 = ((mkb >> b1) & 1u) ? 1e-20f : __expf(l1);
                    }
                    float red[6];
                    red[0] = e0; red[1] = e0*x00; red[2] = e0*x01;
                    red[3] = e1; red[4] = e1*x10; red[5] = e1*x11;
                    wsumv<6>(red);
                    float inv0 = 1.f/red[0], inv1 = 1.f/red[3];
                    float at0 = e0*inv0, at1 = e1*inv1;
                    float al0 = red[1]*inv0, be0 = red[2]*inv0;
                    float al1 = red[4]*inv1, be1 = red[5]*inv1;

                    float L00 = al0*w0_s[lane]      + be0*w1_s[lane];
                    float L01 = al0*w0_s[32+lane]   + be0*w1_s[32+lane];
                    float P00 = al0*w0W_s[lane]     + be0*w1W_s[lane];
                    float P01 = al0*w0W_s[32+lane]  + be0*w1W_s[32+lane];
                    float L10 = al1*w0_s[lane]      + be1*w1_s[lane];
                    float L11 = al1*w0_s[32+lane]   + be1*w1_s[32+lane];
                    float P10 = al1*w0W_s[lane]     + be1*w1W_s[lane];
                    float P11 = al1*w0W_s[32+lane]  + be1*w1W_s[32+lane];
                    #pragma unroll
                    for (int k=0;k<16;k++){
                        float ak0 = __shfl_sync(FULLM, at0, k);
                        float ak1 = __shfl_sync(FULLM, at1, k);
                        float w0v = myT[k*64 + lane];
                        float w1v = myT[k*64 + 32 + lane];
                        L00 = fmaf(ak0, rsp0[k], L00);
                        L01 = fmaf(ak0, rsp1[k], L01);
                        L10 = fmaf(ak1, rsp0[k], L10);
                        L11 = fmaf(ak1, rsp1[k], L11);
                        P00 = fmaf(ak0, w0v, P00);
                        P01 = fmaf(ak0, w1v, P01);
                        P10 = fmaf(ak1, w0v, P10);
                        P11 = fmaf(ak1, w1v, P11);
                    }
                    float rl[4];
                    rl[0] = L00 + L01;
                    rl[1] = L00*L00 + L01*L01;
                    rl[2] = L10 + L11;
                    rl[3] = L10*L10 + L11*L11;
                    wsumv<4>(rl);

                    float mean0 = (rl[0] + sgA)*(1.f/192.f);
                    float var0  = (rl[1] + sg2A)*(1.f/192.f) - mean0*mean0;
                    float rstd0 = rsqrtf(var0 + 1e-5f);
                    float h00 = fmaf(rstd0, (P00+PgA0) - mean0*gcol_s[lane],    cadd_s[lane]);
                    float h01 = fmaf(rstd0, (P01+PgA1) - mean0*gcol_s[32+lane], cadd_s[32+lane]);
                    float g00 = 0.5f*h00*(1.f + erff(h00*0.70710678118654752f));
                    float g01 = 0.5f*h01*(1.f + erff(h01*0.70710678118654752f));

                    float mean1 = (rl[2] + sgB)*(1.f/192.f);
                    float var1  = (rl[3] + sg2B)*(1.f/192.f) - mean1*mean1;
                    float rstd1 = rsqrtf(var1 + 1e-5f);
                    float h10 = fmaf(rstd1, (P10+PgB0) - mean1*gcol_s[lane],    cadd_s[lane]);
                    float h11 = fmaf(rstd1, (P11+PgB1) - mean1*gcol_s[32+lane], cadd_s[32+lane]);
                    float g10 = 0.5f*h10*(1.f + erff(h10*0.70710678118654752f));
                    float g11 = 0.5f*h11*(1.f + erff(h11*0.70710678118654752f));

                    float pr[2];
                    pr[0] = fmaf(g00, wm2_s[lane], g01*wm2_s[32+lane]);
                    pr[1] = fmaf(g10, wm2_s[lane], g11*wm2_s[32+lane]);
                    wsumv<2>(pr);
                    if (lane == 0){
                        out[b0*NS + n] = ((mbn >> b0) & 1u) ? (pr[0] + bm2v) : 0.f;
                        out[b1*NS + n] = ((mbn >> b1) & 1u) ? (pr[1] + bm2v) : 0.f;
                    }
                }
            }
        }
    }
}

// ------------------------- launch -------------------------
extern "C" void kernel_launch(void* const* d_in, const int* in_sizes, int n_in,
                              void* d_out, int out_size){
    const float* xf    = (const float*)d_in[0];
    const float* latent= (const float*)d_in[1];
    const float* pos   = (const float*)d_in[2];
    const float* femb  = (const float*)d_in[3];
    const float* Wnbr  = (const float*)d_in[4];
    const float* bnbr  = (const float*)d_in[5];
    const float* Wql   = (const float*)d_in[6];
    const float* bql   = (const float*)d_in[7];
    const float* Wlat  = (const float*)d_in[8];
    const float* blat  = (const float*)d_in[9];
    const float* Wlf   = (const float*)d_in[10];
    const float* blf   = (const float*)d_in[11];
    const float* Wqg   = (const float*)d_in[12];
    const float* bqg   = (const float*)d_in[13];
    const float* Wk    = (const float*)d_in[14];
    const float* bk    = (const float*)d_in[15];
    const float* Wv    = (const float*)d_in[16];
    const float* bv    = (const float*)d_in[17];
    const float* Wgo   = (const float*)d_in[18];
    const float* bgo   = (const float*)d_in[19];
    const float* lng   = (const float*)d_in[20];
    const float* lnb   = (const float*)d_in[21];
    const float* Wm1   = (const float*)d_in[22];
    const float* bm1   = (const float*)d_in[23];
    const float* Wm2   = (const float*)d_in[24];
    const float* bm2   = (const float*)d_in[25];
    const int* mask    = (const int*)d_in[26];
    const int* knn     = (const int*)d_in[27];
    const int* fid     = (const int*)d_in[28];
    float* out = (float*)d_out;

    static int smem_sz = 23580*4;
    cudaFuncSetAttribute(kAll, cudaFuncAttributeMaxDynamicSharedMemorySize, smem_sz);

    kAll<<<NBLK, 512, smem_sz>>>(
        xf, latent, pos, femb, Wnbr, bnbr, Wql, bql, Wlat, blat, Wlf, blf,
        Wqg, bqg, Wk, bk, Wv, bv, Wgo, bgo, lng, lnb, Wm1, bm1, Wm2, bm2,
        mask, knn, fid, out);
}